// round 9
// baseline (speedup 1.0000x reference)
#include <cuda_runtime.h>
#include <cuda_fp16.h>
#include <float.h>
#include <limits.h>
#include <stdint.h>

// VectorQuantizerEMA forward (eval mode).
//   d_in[0] = X [65536, 256] f32,  d_in[1] = E [1024, 256] f32
//   out (f32): [quantized_st 16777216 | loss 1 | indices 65536]
//
// Phase 1: SINGLE-PASS fp16 scoring GEMM on mma.sync m16n8k16 (proxy noise
//   sigma_dist ~2e-2; 3x fewer MMAs than the R5/R8 bf16 hi/lo split).
//   ||e||^2 folded via 2 augmented K-cols (2-term fp16 cascade).
//   Per-row TOP-8 candidates (capture failure ~1e-11 rows at this sigma).
//   4 n-tiles = 4 independent MMA chains; ldmatrix.x4 loads 2 tiles/op.
//   E chunks double-buffered via cp.async.
// Phase 2: exact fp64 rescore of 8 candidates, diff form (R2-validated).
// Epilogue: identical fp32 math to the reference (bit-exact vs R2/R5/R8).
//
// NOTE: harness compiles at compute_103 (no 'a'): tcgen05/TMEM unavailable;
// mma.sync + ldmatrix + cp.async are baseline PTX and work. Legacy HMMA
// throughput floor measured at ~37 cyc per warp-MMA (R5/R8) -> MMA count
// is the only lever; this kernel cuts it 3x.

#define NROWS    65536
#define DDIM     256
#define KAUG     272               // 256 + 16 (cols 256/257 carry -|e|^2/2 cascade)
#define KSTEPS   (KAUG / 16)       // 17
#define KCODES   1024
#define M_TILE   128
#define THREADS  256
#define WARPS    8
#define CCHUNK   32                // codes per smem chunk
#define NCHUNKS  (KCODES / CCHUNK) // 32
#define ESTRIDE  560               // bytes/row: 280 fp16 (272 used + pad)
#define X_BYTES  (M_TILE * ESTRIDE)       // 71680
#define ECH      (CCHUNK * ESTRIDE)       // 17920 per chunk (single fp16 plane)
#define OFF_X    0
#define OFF_E    X_BYTES
#define DYN_SMEM (X_BYTES + 2 * ECH)      // 107520

__device__ double g_loss_accum;
__device__ __align__(16) unsigned char g_Ehf[KCODES * ESTRIDE];  // 573 KB

// ---------------------------------------------------------------------------
__device__ __forceinline__ uint32_t smem_u32(const void* p) {
    uint32_t a;
    asm("{ .reg .u64 t; cvta.to.shared.u64 t, %1; cvt.u32.u64 %0, t; }"
        : "=r"(a) : "l"(p));
    return a;
}
__device__ __forceinline__ void ldmatrix_x4(uint32_t& r0, uint32_t& r1,
                                            uint32_t& r2, uint32_t& r3,
                                            uint32_t addr) {
    asm volatile("ldmatrix.sync.aligned.m8n8.x4.shared.b16 {%0,%1,%2,%3}, [%4];"
                 : "=r"(r0), "=r"(r1), "=r"(r2), "=r"(r3) : "r"(addr));
}
__device__ __forceinline__ void mma4(float c[4], const uint32_t a[4],
                                     uint32_t b0, uint32_t b1) {
    asm volatile(
        "mma.sync.aligned.m16n8k16.row.col.f32.f16.f16.f32 "
        "{%0,%1,%2,%3}, {%4,%5,%6,%7}, {%8,%9}, {%0,%1,%2,%3};"
        : "+f"(c[0]), "+f"(c[1]), "+f"(c[2]), "+f"(c[3])
        : "r"(a[0]), "r"(a[1]), "r"(a[2]), "r"(a[3]), "r"(b0), "r"(b1));
}
#define CP16(dst, src) \
    asm volatile("cp.async.cg.shared.global [%0], [%1], 16;" \
                 :: "r"(dst), "l"(src) : "memory")
#define CP_COMMIT() asm volatile("cp.async.commit_group;" ::: "memory")
#define CP_WAIT(n)  asm volatile("cp.async.wait_group %0;" :: "n"(n) : "memory")

// sorted top-8 by score desc; tie -> lower code index. Fast path: 1 compare.
// (in-scan, codes ascend per lane, so tie-break also keeps first occurrence)
__device__ __forceinline__ void ins8(float s, int c, float v[8], int ix[8]) {
    if (!(s > v[7] || (s == v[7] && c < ix[7]))) return;
#pragma unroll
    for (int p = 7; p > 0; --p) {
        if (s > v[p - 1] || (s == v[p - 1] && c < ix[p - 1])) {
            v[p] = v[p - 1]; ix[p] = ix[p - 1];
        } else {
            v[p] = s; ix[p] = c; return;
        }
    }
    v[0] = s; ix[0] = c;
}

// ---------------------------------------------------------------------------
// prep: E -> fp16 rows of 280 (272 used); aug cols 256/257 carry a 2-term
// fp16 cascade of -|e|^2/2. One warp per code.
// ---------------------------------------------------------------------------
__global__ void vq_prep(const float* __restrict__ E) {
    const int w = threadIdx.x >> 5, lane = threadIdx.x & 31;
    const int code = blockIdx.x * 8 + w;
    if (blockIdx.x == 0 && threadIdx.x == 0) g_loss_accum = 0.0;

    const float4* e4 = reinterpret_cast<const float4*>(E + (size_t)code * DDIM);
    float4 va = e4[lane * 2], vb = e4[lane * 2 + 1];

    __half2 p0 = __floats2half2_rn(va.x, va.y);
    __half2 p1 = __floats2half2_rn(va.z, va.w);
    __half2 p2 = __floats2half2_rn(vb.x, vb.y);
    __half2 p3 = __floats2half2_rn(vb.z, vb.w);
    uint4 out;
    out.x = *reinterpret_cast<uint32_t*>(&p0);
    out.y = *reinterpret_cast<uint32_t*>(&p1);
    out.z = *reinterpret_cast<uint32_t*>(&p2);
    out.w = *reinterpret_cast<uint32_t*>(&p3);
    *reinterpret_cast<uint4*>(g_Ehf + (size_t)code * ESTRIDE + lane * 16) = out;

    double s = 0.0;
    s += (double)va.x * va.x; s += (double)va.y * va.y;
    s += (double)va.z * va.z; s += (double)va.w * va.w;
    s += (double)vb.x * vb.x; s += (double)vb.y * vb.y;
    s += (double)vb.z * vb.z; s += (double)vb.w * vb.w;
#pragma unroll
    for (int o = 16; o >= 1; o >>= 1)
        s += __shfl_xor_sync(0xffffffffu, s, o);

    if (lane == 0) {
        double d = -0.5 * s;
        __half h1 = __float2half_rn((float)d);
        d -= (double)__half2float(h1);
        __half h2 = __float2half_rn((float)d);
        uint32_t w0 = (uint32_t)*reinterpret_cast<unsigned short*>(&h1) |
                      ((uint32_t)*reinterpret_cast<unsigned short*>(&h2) << 16);
        unsigned char* b = g_Ehf + (size_t)code * ESTRIDE + 512;
        *reinterpret_cast<uint4*>(b +  0) = make_uint4(w0, 0u, 0u, 0u);
        *reinterpret_cast<uint4*>(b + 16) = make_uint4(0u, 0u, 0u, 0u);
        *reinterpret_cast<uint4*>(b + 32) = make_uint4(0u, 0u, 0u, 0u);
    }
}

// ---------------------------------------------------------------------------
__device__ __forceinline__ void prefetch_chunk(uint32_t dst, int chunk, int tid) {
    const unsigned char* src = g_Ehf + (size_t)chunk * ECH;
#pragma unroll 1
    for (int i = tid; i < ECH / 16; i += THREADS)
        CP16(dst + (uint32_t)i * 16u, src + (size_t)i * 16);
    CP_COMMIT();
}

// ---------------------------------------------------------------------------
// main: 512 CTAs x 256 threads (8 warps); warp w owns rows w*16 .. w*16+15.
// ---------------------------------------------------------------------------
__global__ __launch_bounds__(THREADS, 1)
void vq_main_mma(const float* __restrict__ X, const float* __restrict__ E,
                 float* __restrict__ outQ, float* __restrict__ outIdx) {
    extern __shared__ __align__(16) unsigned char sm[];
    __shared__ int   sCand[M_TILE][8];
    __shared__ int   sWin[M_TILE];
    __shared__ float sRed[WARPS];

    const int tid  = threadIdx.x;
    const int w    = tid >> 5;
    const int lane = tid & 31;
    const int rowbase = blockIdx.x * M_TILE;

    const uint32_t sm_u = smem_u32(sm);
    const uint32_t Eu   = sm_u + OFF_E;

    // kick off E chunk 0 prefetch immediately (disjoint from X staging)
    prefetch_chunk(Eu, 0, tid);

    // ---- stage X tile: f32 -> fp16 rows of 280 + aug cols (1.0, 1.0) ------
    for (int i = tid; i < M_TILE * 3; i += THREADS) {
        int r = i / 3, part = i % 3;
        uint4 val = (part == 0) ? make_uint4(0x3C003C00u, 0u, 0u, 0u)
                                : make_uint4(0u, 0u, 0u, 0u);
        *reinterpret_cast<uint4*>(sm + OFF_X + r * ESTRIDE + 512 + part * 16) = val;
    }
    {
        const float4* xg = reinterpret_cast<const float4*>(X + (size_t)rowbase * DDIM);
        for (int i = tid; i < M_TILE * (DDIM / 4); i += THREADS) {
            int r = i >> 6, c4 = i & 63;
            float4 v = xg[i];
            __half2 q0 = __floats2half2_rn(v.x, v.y);
            __half2 q1 = __floats2half2_rn(v.z, v.w);
            uint2 o;
            o.x = *reinterpret_cast<uint32_t*>(&q0);
            o.y = *reinterpret_cast<uint32_t*>(&q1);
            *reinterpret_cast<uint2*>(sm + OFF_X + r * ESTRIDE + c4 * 8) = o;
        }
    }
    __syncthreads();

    // ---- register-resident A fragments (17 ksteps x 4 regs) ---------------
    uint32_t ah[KSTEPS][4];
    {
        uint32_t off = (uint32_t)(w * 16 + (lane & 15)) * ESTRIDE +
                       (uint32_t)((lane >> 4) * 16);
#pragma unroll
        for (int s = 0; s < KSTEPS; ++s)
            ldmatrix_x4(ah[s][0], ah[s][1], ah[s][2], ah[s][3],
                        sm_u + OFF_X + off + s * 32);
    }

    // ---- score all codes; per-thread running top-8 for rows (A, A+8) ------
    float vA[8], vB[8];
    int ixA[8], ixB[8];
#pragma unroll
    for (int j = 0; j < 8; ++j) {
        vA[j] = -FLT_MAX; vB[j] = -FLT_MAX;
        ixA[j] = INT_MAX; ixB[j] = INT_MAX;
    }

    // ldmatrix.x4 B address: matrices {tile k0-7, tile k8-15, tile+1 k0-7,
    // tile+1 k8-15}; lane groups of 8 supply the row addresses.
    const uint32_t brow4 = (uint32_t)(lane & 7) * ESTRIDE +
                           (uint32_t)(((lane >> 3) & 1) * 16) +
                           (uint32_t)((lane >> 4) * 8) * ESTRIDE;

    for (int chunk = 0; chunk < NCHUNKS; ++chunk) {
        const uint32_t buf = Eu + (uint32_t)(chunk & 1) * ECH;
        if (chunk + 1 < NCHUNKS) {
            prefetch_chunk(Eu + (uint32_t)((chunk + 1) & 1) * ECH, chunk + 1, tid);
            CP_WAIT(1);               // current buffer complete
        } else {
            CP_WAIT(0);
        }
        __syncthreads();

        // 4 n-tiles of 8 codes, 4 independent accumulator chains
        float ac0[4] = {0.f, 0.f, 0.f, 0.f}, ac1[4] = {0.f, 0.f, 0.f, 0.f};
        float ac2[4] = {0.f, 0.f, 0.f, 0.f}, ac3[4] = {0.f, 0.f, 0.f, 0.f};
        const uint32_t b01 = buf + brow4;              // tiles 0,1
        const uint32_t b23 = b01 + 16u * ESTRIDE;      // tiles 2,3
#pragma unroll
        for (int s = 0; s < KSTEPS; ++s) {
            uint32_t b00, b01r, b10, b11, b20, b21, b30, b31;
            ldmatrix_x4(b00, b01r, b10, b11, b01 + s * 32);
            ldmatrix_x4(b20, b21,  b30, b31, b23 + s * 32);
            mma4(ac0, ah[s], b00, b01r);
            mma4(ac1, ah[s], b10, b11);
            mma4(ac2, ah[s], b20, b21);
            mma4(ac3, ah[s], b30, b31);
        }
        const int cb = chunk * CCHUNK + (lane & 3) * 2;
        ins8(ac0[0], cb +  0, vA, ixA); ins8(ac0[1], cb +  1, vA, ixA);
        ins8(ac0[2], cb +  0, vB, ixB); ins8(ac0[3], cb +  1, vB, ixB);
        ins8(ac1[0], cb +  8, vA, ixA); ins8(ac1[1], cb +  9, vA, ixA);
        ins8(ac1[2], cb +  8, vB, ixB); ins8(ac1[3], cb +  9, vB, ixB);
        ins8(ac2[0], cb + 16, vA, ixA); ins8(ac2[1], cb + 17, vA, ixA);
        ins8(ac2[2], cb + 16, vB, ixB); ins8(ac2[3], cb + 17, vB, ixB);
        ins8(ac3[0], cb + 24, vA, ixA); ins8(ac3[1], cb + 25, vA, ixA);
        ins8(ac3[2], cb + 24, vB, ixB); ins8(ac3[3], cb + 25, vB, ixB);
        __syncthreads();              // done reading buf before it is refilled
    }

    // ---- merge top-8 across the 4 lanes sharing each row ------------------
#pragma unroll
    for (int o = 1; o <= 2; o <<= 1) {
#pragma unroll
        for (int j = 0; j < 8; ++j) {
            float ovA = __shfl_xor_sync(0xffffffffu, vA[j], o);
            int   oiA = __shfl_xor_sync(0xffffffffu, ixA[j], o);
            float ovB = __shfl_xor_sync(0xffffffffu, vB[j], o);
            int   oiB = __shfl_xor_sync(0xffffffffu, ixB[j], o);
            ins8(ovA, oiA, vA, ixA);
            ins8(ovB, oiB, vB, ixB);
        }
    }
    if ((lane & 3) == 0) {
        int rA = w * 16 + (lane >> 2);
#pragma unroll
        for (int j = 0; j < 8; ++j) {
            sCand[rA][j]     = ixA[j];
            sCand[rA + 8][j] = ixB[j];
        }
    }
    __syncthreads();

    // ---- Phase 2: exact fp64 rescore (2 threads/row x 4 cands each) -------
    {
        int r = tid >> 1;
        const float4* x4 = reinterpret_cast<const float4*>(X + (size_t)(rowbase + r) * DDIM);
        double best = 1.0e300;
        int    bc   = INT_MAX;
#pragma unroll 1
        for (int j = 0; j < 4; ++j) {
            int cand = sCand[r][(tid & 1) * 4 + j];
            const float4* ep = reinterpret_cast<const float4*>(E + (size_t)cand * DDIM);
            double dd = 0.0;
#pragma unroll 4
            for (int k = 0; k < DDIM / 4; ++k) {
                float4 xv = x4[k], ev = ep[k];
                double d;
                d = (double)xv.x - (double)ev.x; dd += d * d;
                d = (double)xv.y - (double)ev.y; dd += d * d;
                d = (double)xv.z - (double)ev.z; dd += d * d;
                d = (double)xv.w - (double)ev.w; dd += d * d;
            }
            if (dd < best || (dd == best && cand < bc)) { best = dd; bc = cand; }
        }
        double od = __shfl_xor_sync(0xffffffffu, best, 1);
        int    oc = __shfl_xor_sync(0xffffffffu, bc, 1);
        if (od < best || (od == best && oc < bc)) { bc = oc; }
        if ((tid & 1) == 0) sWin[r] = bc;
    }
    __syncthreads();

    // ---- epilogue: gather + straight-through + loss (bit-exact to R2) -----
    float lsum = 0.0f;
    {
        const float4* xg = reinterpret_cast<const float4*>(X + (size_t)rowbase * DDIM);
        for (int i = tid; i < M_TILE * (DDIM / 4); i += THREADS) {
            int r = i >> 6, c4 = i & 63;
            int idx = sWin[r];
            float4 e = *reinterpret_cast<const float4*>(E + (size_t)idx * DDIM + c4 * 4);
            float4 x = xg[i];
            float4 d, q;
            d.x = e.x - x.x; d.y = e.y - x.y; d.z = e.z - x.z; d.w = e.w - x.w;
            q.x = x.x + d.x; q.y = x.y + d.y; q.z = x.z + d.z; q.w = x.w + d.w;
            lsum += d.x * d.x + d.y * d.y + d.z * d.z + d.w * d.w;
            *reinterpret_cast<float4*>(outQ + (size_t)(rowbase + r) * DDIM + c4 * 4) = q;
        }
    }
    if (tid < M_TILE) outIdx[rowbase + tid] = (float)sWin[tid];

#pragma unroll
    for (int s = 16; s >= 1; s >>= 1)
        lsum += __shfl_xor_sync(0xffffffffu, lsum, s);
    if (lane == 0) sRed[w] = lsum;
    __syncthreads();
    if (tid == 0) {
        float s = 0.0f;
#pragma unroll
        for (int i = 0; i < WARPS; ++i) s += sRed[i];
        atomicAdd(&g_loss_accum, (double)s);
    }
}

// ---------------------------------------------------------------------------
__global__ void vq_finalize(float* __restrict__ outLoss) {
    if (threadIdx.x == 0)
        *outLoss = (float)(g_loss_accum * (1.0 / (double)((size_t)NROWS * DDIM)));
}

// ---------------------------------------------------------------------------
extern "C" void kernel_launch(void* const* d_in, const int* in_sizes, int n_in,
                              void* d_out, int out_size) {
    (void)in_sizes; (void)n_in; (void)out_size;
    const float* X = (const float*)d_in[0];
    const float* E = (const float*)d_in[1];

    float* outQ    = (float*)d_out;
    float* outLoss = outQ + (size_t)NROWS * DDIM;   // 16777216
    float* outIdx  = outLoss + 1;                   // 16777217

    cudaFuncSetAttribute(vq_main_mma, cudaFuncAttributeMaxDynamicSharedMemorySize,
                         DYN_SMEM);

    vq_prep<<<KCODES / 8, 256>>>(E);
    vq_main_mma<<<NROWS / M_TILE, THREADS, DYN_SMEM>>>(X, E, outQ, outIdx);
    vq_finalize<<<1, 32>>>(outLoss);
}

// round 10
// speedup vs baseline: 1.0842x; 1.0842x over previous
#include <cuda_runtime.h>
#include <cuda_fp16.h>
#include <float.h>
#include <limits.h>
#include <stdint.h>

// VectorQuantizerEMA forward (eval mode).
//   d_in[0] = X [65536, 256] f32,  d_in[1] = E [1024, 256] f32
//   out (f32): [quantized_st 16777216 | loss 1 | indices 65536]
//
// Phase 1: SINGLE-PASS fp16 scoring GEMM on mma.sync m16n8k16 (3x fewer
//   MMAs than bf16 hi/lo split). ||e||^2 folded via 2 augmented K-cols.
//   Per-thread LANE-LOCAL top-4 via R8-proven nested-if ladder (register
//   resident -- R9's loop/return ins8 spilled to local memory, 4.8x slower).
//   No cross-lane merge: 4 lanes x top-4 = 16 candidates per row.
//   E chunks double-buffered via cp.async.
// Phase 2: exact fp64 rescore of 16 candidates, diff form (R2-validated).
// Epilogue: identical fp32 math to the reference (bit-exact vs R2/R5/R8).
//
// NOTE: harness compiles at compute_103 (no 'a'): tcgen05/TMEM unavailable;
// mma.sync + ldmatrix + cp.async are baseline PTX and work. Legacy HMMA
// throughput floor ~37 cyc per warp-MMA (measured R5/R8).

#define NROWS    65536
#define DDIM     256
#define KAUG     272               // 256 + 16 (cols 256/257 carry -|e|^2/2 cascade)
#define KSTEPS   (KAUG / 16)       // 17
#define KCODES   1024
#define M_TILE   128
#define THREADS  256
#define WARPS    8
#define CCHUNK   32                // codes per smem chunk
#define NCHUNKS  (KCODES / CCHUNK) // 32
#define ESTRIDE  560               // bytes/row: 280 fp16 (272 used + pad)
#define X_BYTES  (M_TILE * ESTRIDE)       // 71680
#define ECH      (CCHUNK * ESTRIDE)       // 17920 per chunk (single fp16 plane)
#define OFF_X    0
#define OFF_E    X_BYTES
#define DYN_SMEM (X_BYTES + 2 * ECH)      // 107520

__device__ double g_loss_accum;
__device__ __align__(16) unsigned char g_Ehf[KCODES * ESTRIDE];  // 573 KB

// ---------------------------------------------------------------------------
__device__ __forceinline__ uint32_t smem_u32(const void* p) {
    uint32_t a;
    asm("{ .reg .u64 t; cvta.to.shared.u64 t, %1; cvt.u32.u64 %0, t; }"
        : "=r"(a) : "l"(p));
    return a;
}
__device__ __forceinline__ void ldmatrix_x4(uint32_t& r0, uint32_t& r1,
                                            uint32_t& r2, uint32_t& r3,
                                            uint32_t addr) {
    asm volatile("ldmatrix.sync.aligned.m8n8.x4.shared.b16 {%0,%1,%2,%3}, [%4];"
                 : "=r"(r0), "=r"(r1), "=r"(r2), "=r"(r3) : "r"(addr));
}
__device__ __forceinline__ void mma4(float c[4], const uint32_t a[4],
                                     uint32_t b0, uint32_t b1) {
    asm volatile(
        "mma.sync.aligned.m16n8k16.row.col.f32.f16.f16.f32 "
        "{%0,%1,%2,%3}, {%4,%5,%6,%7}, {%8,%9}, {%0,%1,%2,%3};"
        : "+f"(c[0]), "+f"(c[1]), "+f"(c[2]), "+f"(c[3])
        : "r"(a[0]), "r"(a[1]), "r"(a[2]), "r"(a[3]), "r"(b0), "r"(b1));
}
#define CP16(dst, src) \
    asm volatile("cp.async.cg.shared.global [%0], [%1], 16;" \
                 :: "r"(dst), "l"(src) : "memory")
#define CP_COMMIT() asm volatile("cp.async.commit_group;" ::: "memory")
#define CP_WAIT(n)  asm volatile("cp.async.wait_group %0;" :: "n"(n) : "memory")

// sorted top-4 by score desc (R8-proven: constant-index nested ifs, flattens
// to predicated selects, NO loops/returns -> stays in registers).
// Strict '>' only: in-lane codes ascend, so ties keep the earlier code.
__device__ __forceinline__ void ins4(float s, int c, float v[4], int ix[4]) {
    if (s > v[3]) {
        if (s > v[2]) {
            v[3] = v[2]; ix[3] = ix[2];
            if (s > v[1]) {
                v[2] = v[1]; ix[2] = ix[1];
                if (s > v[0]) { v[1] = v[0]; ix[1] = ix[0]; v[0] = s; ix[0] = c; }
                else          { v[1] = s; ix[1] = c; }
            } else { v[2] = s; ix[2] = c; }
        } else { v[3] = s; ix[3] = c; }
    }
}

// ---------------------------------------------------------------------------
// prep: E -> fp16 rows of 280 (272 used); aug cols 256/257 carry a 2-term
// fp16 cascade of -|e|^2/2. One warp per code.
// ---------------------------------------------------------------------------
__global__ void vq_prep(const float* __restrict__ E) {
    const int w = threadIdx.x >> 5, lane = threadIdx.x & 31;
    const int code = blockIdx.x * 8 + w;
    if (blockIdx.x == 0 && threadIdx.x == 0) g_loss_accum = 0.0;

    const float4* e4 = reinterpret_cast<const float4*>(E + (size_t)code * DDIM);
    float4 va = e4[lane * 2], vb = e4[lane * 2 + 1];

    __half2 p0 = __floats2half2_rn(va.x, va.y);
    __half2 p1 = __floats2half2_rn(va.z, va.w);
    __half2 p2 = __floats2half2_rn(vb.x, vb.y);
    __half2 p3 = __floats2half2_rn(vb.z, vb.w);
    uint4 out;
    out.x = *reinterpret_cast<uint32_t*>(&p0);
    out.y = *reinterpret_cast<uint32_t*>(&p1);
    out.z = *reinterpret_cast<uint32_t*>(&p2);
    out.w = *reinterpret_cast<uint32_t*>(&p3);
    *reinterpret_cast<uint4*>(g_Ehf + (size_t)code * ESTRIDE + lane * 16) = out;

    double s = 0.0;
    s += (double)va.x * va.x; s += (double)va.y * va.y;
    s += (double)va.z * va.z; s += (double)va.w * va.w;
    s += (double)vb.x * vb.x; s += (double)vb.y * vb.y;
    s += (double)vb.z * vb.z; s += (double)vb.w * vb.w;
#pragma unroll
    for (int o = 16; o >= 1; o >>= 1)
        s += __shfl_xor_sync(0xffffffffu, s, o);

    if (lane == 0) {
        double d = -0.5 * s;
        __half h1 = __float2half_rn((float)d);
        d -= (double)__half2float(h1);
        __half h2 = __float2half_rn((float)d);
        uint32_t w0 = (uint32_t)*reinterpret_cast<unsigned short*>(&h1) |
                      ((uint32_t)*reinterpret_cast<unsigned short*>(&h2) << 16);
        unsigned char* b = g_Ehf + (size_t)code * ESTRIDE + 512;
        *reinterpret_cast<uint4*>(b +  0) = make_uint4(w0, 0u, 0u, 0u);
        *reinterpret_cast<uint4*>(b + 16) = make_uint4(0u, 0u, 0u, 0u);
        *reinterpret_cast<uint4*>(b + 32) = make_uint4(0u, 0u, 0u, 0u);
    }
}

// ---------------------------------------------------------------------------
__device__ __forceinline__ void prefetch_chunk(uint32_t dst, int chunk, int tid) {
    const unsigned char* src = g_Ehf + (size_t)chunk * ECH;
#pragma unroll 1
    for (int i = tid; i < ECH / 16; i += THREADS)
        CP16(dst + (uint32_t)i * 16u, src + (size_t)i * 16);
    CP_COMMIT();
}

// ---------------------------------------------------------------------------
// main: 512 CTAs x 256 threads (8 warps); warp w owns rows w*16 .. w*16+15.
// ---------------------------------------------------------------------------
__global__ __launch_bounds__(THREADS, 1)
void vq_main_mma(const float* __restrict__ X, const float* __restrict__ E,
                 float* __restrict__ outQ, float* __restrict__ outIdx) {
    extern __shared__ __align__(16) unsigned char sm[];
    __shared__ int   sCand[M_TILE][16];
    __shared__ int   sWin[M_TILE];
    __shared__ float sRed[WARPS];

    const int tid  = threadIdx.x;
    const int w    = tid >> 5;
    const int lane = tid & 31;
    const int rowbase = blockIdx.x * M_TILE;

    const uint32_t sm_u = smem_u32(sm);
    const uint32_t Eu   = sm_u + OFF_E;

    // kick off E chunk 0 prefetch immediately (disjoint from X staging)
    prefetch_chunk(Eu, 0, tid);

    // ---- stage X tile: f32 -> fp16 rows of 280 + aug cols (1.0, 1.0) ------
    for (int i = tid; i < M_TILE * 3; i += THREADS) {
        int r = i / 3, part = i % 3;
        uint4 val = (part == 0) ? make_uint4(0x3C003C00u, 0u, 0u, 0u)
                                : make_uint4(0u, 0u, 0u, 0u);
        *reinterpret_cast<uint4*>(sm + OFF_X + r * ESTRIDE + 512 + part * 16) = val;
    }
    {
        const float4* xg = reinterpret_cast<const float4*>(X + (size_t)rowbase * DDIM);
        for (int i = tid; i < M_TILE * (DDIM / 4); i += THREADS) {
            int r = i >> 6, c4 = i & 63;
            float4 v = xg[i];
            __half2 q0 = __floats2half2_rn(v.x, v.y);
            __half2 q1 = __floats2half2_rn(v.z, v.w);
            uint2 o;
            o.x = *reinterpret_cast<uint32_t*>(&q0);
            o.y = *reinterpret_cast<uint32_t*>(&q1);
            *reinterpret_cast<uint2*>(sm + OFF_X + r * ESTRIDE + c4 * 8) = o;
        }
    }
    __syncthreads();

    // ---- register-resident A fragments (17 ksteps x 4 regs) ---------------
    uint32_t ah[KSTEPS][4];
    {
        uint32_t off = (uint32_t)(w * 16 + (lane & 15)) * ESTRIDE +
                       (uint32_t)((lane >> 4) * 16);
#pragma unroll
        for (int s = 0; s < KSTEPS; ++s)
            ldmatrix_x4(ah[s][0], ah[s][1], ah[s][2], ah[s][3],
                        sm_u + OFF_X + off + s * 32);
    }

    // ---- score all codes; lane-local top-4 for rows (A, A+8) --------------
    float vA[4] = {-FLT_MAX, -FLT_MAX, -FLT_MAX, -FLT_MAX};
    float vB[4] = {-FLT_MAX, -FLT_MAX, -FLT_MAX, -FLT_MAX};
    int ixA[4] = {INT_MAX, INT_MAX, INT_MAX, INT_MAX};
    int ixB[4] = {INT_MAX, INT_MAX, INT_MAX, INT_MAX};

    // ldmatrix.x4 B address: matrices {tile k0-7, tile k8-15, tile+1 k0-7,
    // tile+1 k8-15}; lane groups of 8 supply the row addresses.
    const uint32_t brow4 = (uint32_t)(lane & 7) * ESTRIDE +
                           (uint32_t)(((lane >> 3) & 1) * 16) +
                           (uint32_t)((lane >> 4) * 8) * ESTRIDE;

    for (int chunk = 0; chunk < NCHUNKS; ++chunk) {
        const uint32_t buf = Eu + (uint32_t)(chunk & 1) * ECH;
        if (chunk + 1 < NCHUNKS) {
            prefetch_chunk(Eu + (uint32_t)((chunk + 1) & 1) * ECH, chunk + 1, tid);
            CP_WAIT(1);               // current buffer complete
        } else {
            CP_WAIT(0);
        }
        __syncthreads();

        // 4 n-tiles of 8 codes, 4 independent accumulator chains
        float ac0[4] = {0.f, 0.f, 0.f, 0.f}, ac1[4] = {0.f, 0.f, 0.f, 0.f};
        float ac2[4] = {0.f, 0.f, 0.f, 0.f}, ac3[4] = {0.f, 0.f, 0.f, 0.f};
        const uint32_t b01 = buf + brow4;              // tiles 0,1
        const uint32_t b23 = b01 + 16u * ESTRIDE;      // tiles 2,3
#pragma unroll
        for (int s = 0; s < KSTEPS; ++s) {
            uint32_t b00, b01r, b10, b11, b20, b21, b30, b31;
            ldmatrix_x4(b00, b01r, b10, b11, b01 + s * 32);
            ldmatrix_x4(b20, b21,  b30, b31, b23 + s * 32);
            mma4(ac0, ah[s], b00, b01r);
            mma4(ac1, ah[s], b10, b11);
            mma4(ac2, ah[s], b20, b21);
            mma4(ac3, ah[s], b30, b31);
        }
        const int cb = chunk * CCHUNK + (lane & 3) * 2;
        ins4(ac0[0], cb +  0, vA, ixA); ins4(ac0[1], cb +  1, vA, ixA);
        ins4(ac0[2], cb +  0, vB, ixB); ins4(ac0[3], cb +  1, vB, ixB);
        ins4(ac1[0], cb +  8, vA, ixA); ins4(ac1[1], cb +  9, vA, ixA);
        ins4(ac1[2], cb +  8, vB, ixB); ins4(ac1[3], cb +  9, vB, ixB);
        ins4(ac2[0], cb + 16, vA, ixA); ins4(ac2[1], cb + 17, vA, ixA);
        ins4(ac2[2], cb + 16, vB, ixB); ins4(ac2[3], cb + 17, vB, ixB);
        ins4(ac3[0], cb + 24, vA, ixA); ins4(ac3[1], cb + 25, vA, ixA);
        ins4(ac3[2], cb + 24, vB, ixB); ins4(ac3[3], cb + 25, vB, ixB);
        __syncthreads();              // done reading buf before it is refilled
    }

    // ---- NO cross-lane merge: each lane writes its own top-4 --------------
    // Lanes see disjoint code subsets, so the 16 slots hold 16 distinct
    // candidates; the true argmin is in its lane's top-4 (a.s.).
    {
        int rA = w * 16 + (lane >> 2);
        int sl = (lane & 3) * 4;
#pragma unroll
        for (int j = 0; j < 4; ++j) {
            sCand[rA][sl + j]     = ixA[j];
            sCand[rA + 8][sl + j] = ixB[j];
        }
    }
    __syncthreads();

    // ---- Phase 2: exact fp64 rescore (2 threads/row x 8 cands each) -------
    {
        int r = tid >> 1;
        const float4* x4 = reinterpret_cast<const float4*>(X + (size_t)(rowbase + r) * DDIM);
        double best = 1.0e300;
        int    bc   = INT_MAX;
#pragma unroll 1
        for (int j = 0; j < 8; ++j) {
            int cand = sCand[r][(tid & 1) * 8 + j];
            const float4* ep = reinterpret_cast<const float4*>(E + (size_t)cand * DDIM);
            double dd = 0.0;
#pragma unroll 4
            for (int k = 0; k < DDIM / 4; ++k) {
                float4 xv = x4[k], ev = ep[k];
                double d;
                d = (double)xv.x - (double)ev.x; dd += d * d;
                d = (double)xv.y - (double)ev.y; dd += d * d;
                d = (double)xv.z - (double)ev.z; dd += d * d;
                d = (double)xv.w - (double)ev.w; dd += d * d;
            }
            if (dd < best || (dd == best && cand < bc)) { best = dd; bc = cand; }
        }
        double od = __shfl_xor_sync(0xffffffffu, best, 1);
        int    oc = __shfl_xor_sync(0xffffffffu, bc, 1);
        if (od < best || (od == best && oc < bc)) { bc = oc; }
        if ((tid & 1) == 0) sWin[r] = bc;
    }
    __syncthreads();

    // ---- epilogue: gather + straight-through + loss (bit-exact to R2) -----
    float lsum = 0.0f;
    {
        const float4* xg = reinterpret_cast<const float4*>(X + (size_t)rowbase * DDIM);
        for (int i = tid; i < M_TILE * (DDIM / 4); i += THREADS) {
            int r = i >> 6, c4 = i & 63;
            int idx = sWin[r];
            float4 e = *reinterpret_cast<const float4*>(E + (size_t)idx * DDIM + c4 * 4);
            float4 x = xg[i];
            float4 d, q;
            d.x = e.x - x.x; d.y = e.y - x.y; d.z = e.z - x.z; d.w = e.w - x.w;
            q.x = x.x + d.x; q.y = x.y + d.y; q.z = x.z + d.z; q.w = x.w + d.w;
            lsum += d.x * d.x + d.y * d.y + d.z * d.z + d.w * d.w;
            *reinterpret_cast<float4*>(outQ + (size_t)(rowbase + r) * DDIM + c4 * 4) = q;
        }
    }
    if (tid < M_TILE) outIdx[rowbase + tid] = (float)sWin[tid];

#pragma unroll
    for (int s = 16; s >= 1; s >>= 1)
        lsum += __shfl_xor_sync(0xffffffffu, lsum, s);
    if (lane == 0) sRed[w] = lsum;
    __syncthreads();
    if (tid == 0) {
        float s = 0.0f;
#pragma unroll
        for (int i = 0; i < WARPS; ++i) s += sRed[i];
        atomicAdd(&g_loss_accum, (double)s);
    }
}

// ---------------------------------------------------------------------------
__global__ void vq_finalize(float* __restrict__ outLoss) {
    if (threadIdx.x == 0)
        *outLoss = (float)(g_loss_accum * (1.0 / (double)((size_t)NROWS * DDIM)));
}

// ---------------------------------------------------------------------------
extern "C" void kernel_launch(void* const* d_in, const int* in_sizes, int n_in,
                              void* d_out, int out_size) {
    (void)in_sizes; (void)n_in; (void)out_size;
    const float* X = (const float*)d_in[0];
    const float* E = (const float*)d_in[1];

    float* outQ    = (float*)d_out;
    float* outLoss = outQ + (size_t)NROWS * DDIM;   // 16777216
    float* outIdx  = outLoss + 1;                   // 16777217

    cudaFuncSetAttribute(vq_main_mma, cudaFuncAttributeMaxDynamicSharedMemorySize,
                         DYN_SMEM);

    vq_prep<<<KCODES / 8, 256>>>(E);
    vq_main_mma<<<NROWS / M_TILE, THREADS, DYN_SMEM>>>(X, E, outQ, outIdx);
    vq_finalize<<<1, 32>>>(outLoss);
}

// round 11
// speedup vs baseline: 3.2718x; 3.0176x over previous
#include <cuda_runtime.h>
#include <cuda_bf16.h>
#include <float.h>
#include <limits.h>
#include <stdint.h>

// VectorQuantizerEMA forward (eval mode).
//   d_in[0] = X [65536, 256] f32,  d_in[1] = E [1024, 256] f32
//   out (f32): [quantized_st 16777216 | loss 1 | indices 65536]
//
// Phase 1: SINGLE-PASS bf16 scoring GEMM on mma.sync m16n8k16.
//   (R9/R10 showed fp16.f32 mma is ~530cyc/op at compute_103 -> emulated;
//    bf16.f32 measured native at ~40cyc in R5/R8. Same minimal MMA count
//    as R10: 8.9M warp-MMAs.)  ||e||^2 folded via 2 augmented K-cols.
//   Lane-local top-6 (nested-if ladder, register resident) -> 24 disjoint
//   candidates/row, no cross-lane merge. E chunks double-buffered cp.async.
// Phase 2a: fp32 diff-form rescore of 24 cands -> row top-4.
// Phase 2b: exact fp64 diff-form rescore of top-4 (R2/R8-validated).
// Epilogue: identical fp32 math to the reference (bit-exact).
//
// NOTE: harness compiles at compute_103 (no 'a'): tcgen05/TMEM unavailable.

#define NROWS    65536
#define DDIM     256
#define KAUG     272               // 256 + 16 (cols 256/257: -|e|^2/2 cascade)
#define KSTEPS   (KAUG / 16)       // 17
#define KCODES   1024
#define M_TILE   128
#define THREADS  256
#define WARPS    8
#define CCHUNK   32                // codes per smem chunk
#define NCHUNKS  (KCODES / CCHUNK) // 32
#define ESTRIDE  560               // bytes/row: 280 bf16 (272 used + pad)
#define X_BYTES  (M_TILE * ESTRIDE)       // 71680
#define ECH      (CCHUNK * ESTRIDE)       // 17920 per chunk
#define OFF_X    0
#define OFF_E    X_BYTES
#define DYN_SMEM (X_BYTES + 2 * ECH)      // 107520

__device__ double g_loss_accum;
__device__ __align__(16) unsigned char g_Ebf[KCODES * ESTRIDE];  // 573 KB

// ---------------------------------------------------------------------------
__device__ __forceinline__ uint32_t smem_u32(const void* p) {
    uint32_t a;
    asm("{ .reg .u64 t; cvta.to.shared.u64 t, %1; cvt.u32.u64 %0, t; }"
        : "=r"(a) : "l"(p));
    return a;
}
__device__ __forceinline__ void ldmatrix_x4(uint32_t& r0, uint32_t& r1,
                                            uint32_t& r2, uint32_t& r3,
                                            uint32_t addr) {
    asm volatile("ldmatrix.sync.aligned.m8n8.x4.shared.b16 {%0,%1,%2,%3}, [%4];"
                 : "=r"(r0), "=r"(r1), "=r"(r2), "=r"(r3) : "r"(addr));
}
__device__ __forceinline__ void mma4(float c[4], const uint32_t a[4],
                                     uint32_t b0, uint32_t b1) {
    asm volatile(
        "mma.sync.aligned.m16n8k16.row.col.f32.bf16.bf16.f32 "
        "{%0,%1,%2,%3}, {%4,%5,%6,%7}, {%8,%9}, {%0,%1,%2,%3};"
        : "+f"(c[0]), "+f"(c[1]), "+f"(c[2]), "+f"(c[3])
        : "r"(a[0]), "r"(a[1]), "r"(a[2]), "r"(a[3]), "r"(b0), "r"(b1));
}
#define CP16(dst, src) \
    asm volatile("cp.async.cg.shared.global [%0], [%1], 16;" \
                 :: "r"(dst), "l"(src) : "memory")
#define CP_COMMIT() asm volatile("cp.async.commit_group;" ::: "memory")
#define CP_WAIT(n)  asm volatile("cp.async.wait_group %0;" :: "n"(n) : "memory")

// sorted top-6 by score desc (constant-index nested ifs -> predicated
// selects, register resident; R8-proven pattern, NO loops/returns).
// Strict '>' only: in-lane codes ascend, so ties keep the earlier code.
__device__ __forceinline__ void ins6(float s, int c, float v[6], int ix[6]) {
    if (s > v[5]) {
        if (s > v[4]) {
            v[5] = v[4]; ix[5] = ix[4];
            if (s > v[3]) {
                v[4] = v[3]; ix[4] = ix[3];
                if (s > v[2]) {
                    v[3] = v[2]; ix[3] = ix[2];
                    if (s > v[1]) {
                        v[2] = v[1]; ix[2] = ix[1];
                        if (s > v[0]) {
                            v[1] = v[0]; ix[1] = ix[0]; v[0] = s; ix[0] = c;
                        } else { v[1] = s; ix[1] = c; }
                    } else { v[2] = s; ix[2] = c; }
                } else { v[3] = s; ix[3] = c; }
            } else { v[4] = s; ix[4] = c; }
        } else { v[5] = s; ix[5] = c; }
    }
}

// sorted top-4 by distance ASC (min); ties -> lower code index.
__device__ __forceinline__ void ins4min(float d, int c, float v[4], int ix[4]) {
    if (d < v[3] || (d == v[3] && c < ix[3])) {
        if (d < v[2] || (d == v[2] && c < ix[2])) {
            v[3] = v[2]; ix[3] = ix[2];
            if (d < v[1] || (d == v[1] && c < ix[1])) {
                v[2] = v[1]; ix[2] = ix[1];
                if (d < v[0] || (d == v[0] && c < ix[0])) {
                    v[1] = v[0]; ix[1] = ix[0]; v[0] = d; ix[0] = c;
                } else { v[1] = d; ix[1] = c; }
            } else { v[2] = d; ix[2] = c; }
        } else { v[3] = d; ix[3] = c; }
    }
}

// ---------------------------------------------------------------------------
// prep: E -> bf16 rows of 280 (272 used); aug cols 256/257 carry a 2-term
// bf16 cascade of -|e|^2/2 (residual ~5e-4 << score noise). One warp/code.
// ---------------------------------------------------------------------------
__global__ void vq_prep(const float* __restrict__ E) {
    const int w = threadIdx.x >> 5, lane = threadIdx.x & 31;
    const int code = blockIdx.x * 8 + w;
    if (blockIdx.x == 0 && threadIdx.x == 0) g_loss_accum = 0.0;

    const float4* e4 = reinterpret_cast<const float4*>(E + (size_t)code * DDIM);
    float4 va = e4[lane * 2], vb = e4[lane * 2 + 1];

    __nv_bfloat162 p0 = __floats2bfloat162_rn(va.x, va.y);
    __nv_bfloat162 p1 = __floats2bfloat162_rn(va.z, va.w);
    __nv_bfloat162 p2 = __floats2bfloat162_rn(vb.x, vb.y);
    __nv_bfloat162 p3 = __floats2bfloat162_rn(vb.z, vb.w);
    uint4 out;
    out.x = *reinterpret_cast<uint32_t*>(&p0);
    out.y = *reinterpret_cast<uint32_t*>(&p1);
    out.z = *reinterpret_cast<uint32_t*>(&p2);
    out.w = *reinterpret_cast<uint32_t*>(&p3);
    *reinterpret_cast<uint4*>(g_Ebf + (size_t)code * ESTRIDE + lane * 16) = out;

    double s = 0.0;
    s += (double)va.x * va.x; s += (double)va.y * va.y;
    s += (double)va.z * va.z; s += (double)va.w * va.w;
    s += (double)vb.x * vb.x; s += (double)vb.y * vb.y;
    s += (double)vb.z * vb.z; s += (double)vb.w * vb.w;
#pragma unroll
    for (int o = 16; o >= 1; o >>= 1)
        s += __shfl_xor_sync(0xffffffffu, s, o);

    if (lane == 0) {
        double d = -0.5 * s;
        __nv_bfloat16 h1 = __float2bfloat16_rn((float)d);
        d -= (double)__bfloat162float(h1);
        __nv_bfloat16 h2 = __float2bfloat16_rn((float)d);
        uint32_t w0 = (uint32_t)*reinterpret_cast<unsigned short*>(&h1) |
                      ((uint32_t)*reinterpret_cast<unsigned short*>(&h2) << 16);
        unsigned char* b = g_Ebf + (size_t)code * ESTRIDE + 512;
        *reinterpret_cast<uint4*>(b +  0) = make_uint4(w0, 0u, 0u, 0u);
        *reinterpret_cast<uint4*>(b + 16) = make_uint4(0u, 0u, 0u, 0u);
        *reinterpret_cast<uint4*>(b + 32) = make_uint4(0u, 0u, 0u, 0u);
    }
}

// ---------------------------------------------------------------------------
__device__ __forceinline__ void prefetch_chunk(uint32_t dst, int chunk, int tid) {
    const unsigned char* src = g_Ebf + (size_t)chunk * ECH;
#pragma unroll 1
    for (int i = tid; i < ECH / 16; i += THREADS)
        CP16(dst + (uint32_t)i * 16u, src + (size_t)i * 16);
    CP_COMMIT();
}

// ---------------------------------------------------------------------------
// main: 512 CTAs x 256 threads (8 warps); warp w owns rows w*16 .. w*16+15.
// ---------------------------------------------------------------------------
__global__ __launch_bounds__(THREADS, 1)
void vq_main_mma(const float* __restrict__ X, const float* __restrict__ E,
                 float* __restrict__ outQ, float* __restrict__ outIdx) {
    extern __shared__ __align__(16) unsigned char sm[];
    __shared__ int   sCand[M_TILE][24];
    __shared__ int   sWin[M_TILE];
    __shared__ float sRed[WARPS];

    const int tid  = threadIdx.x;
    const int w    = tid >> 5;
    const int lane = tid & 31;
    const int rowbase = blockIdx.x * M_TILE;

    const uint32_t sm_u = smem_u32(sm);
    const uint32_t Eu   = sm_u + OFF_E;

    // kick off E chunk 0 prefetch immediately (disjoint from X staging)
    prefetch_chunk(Eu, 0, tid);

    // ---- stage X tile: f32 -> bf16 rows of 280 + aug cols (1.0, 1.0) ------
    for (int i = tid; i < M_TILE * 3; i += THREADS) {
        int r = i / 3, part = i % 3;
        uint4 val = (part == 0) ? make_uint4(0x3F803F80u, 0u, 0u, 0u)
                                : make_uint4(0u, 0u, 0u, 0u);
        *reinterpret_cast<uint4*>(sm + OFF_X + r * ESTRIDE + 512 + part * 16) = val;
    }
    {
        const float4* xg = reinterpret_cast<const float4*>(X + (size_t)rowbase * DDIM);
        for (int i = tid; i < M_TILE * (DDIM / 4); i += THREADS) {
            int r = i >> 6, c4 = i & 63;
            float4 v = xg[i];
            __nv_bfloat162 q0 = __floats2bfloat162_rn(v.x, v.y);
            __nv_bfloat162 q1 = __floats2bfloat162_rn(v.z, v.w);
            uint2 o;
            o.x = *reinterpret_cast<uint32_t*>(&q0);
            o.y = *reinterpret_cast<uint32_t*>(&q1);
            *reinterpret_cast<uint2*>(sm + OFF_X + r * ESTRIDE + c4 * 8) = o;
        }
    }
    __syncthreads();

    // ---- register-resident A fragments (17 ksteps x 4 regs) ---------------
    uint32_t ah[KSTEPS][4];
    {
        uint32_t off = (uint32_t)(w * 16 + (lane & 15)) * ESTRIDE +
                       (uint32_t)((lane >> 4) * 16);
#pragma unroll
        for (int s = 0; s < KSTEPS; ++s)
            ldmatrix_x4(ah[s][0], ah[s][1], ah[s][2], ah[s][3],
                        sm_u + OFF_X + off + s * 32);
    }

    // ---- score all codes; lane-local top-6 for rows (A, A+8) --------------
    float vA[6] = {-FLT_MAX, -FLT_MAX, -FLT_MAX, -FLT_MAX, -FLT_MAX, -FLT_MAX};
    float vB[6] = {-FLT_MAX, -FLT_MAX, -FLT_MAX, -FLT_MAX, -FLT_MAX, -FLT_MAX};
    int ixA[6] = {INT_MAX, INT_MAX, INT_MAX, INT_MAX, INT_MAX, INT_MAX};
    int ixB[6] = {INT_MAX, INT_MAX, INT_MAX, INT_MAX, INT_MAX, INT_MAX};

    // ldmatrix.x4 B address (validated in R10): matrices {tile k0-7,
    // tile k8-15, tile+1 k0-7, tile+1 k8-15}.
    const uint32_t brow4 = (uint32_t)(lane & 7) * ESTRIDE +
                           (uint32_t)(((lane >> 3) & 1) * 16) +
                           (uint32_t)((lane >> 4) * 8) * ESTRIDE;

    for (int chunk = 0; chunk < NCHUNKS; ++chunk) {
        const uint32_t buf = Eu + (uint32_t)(chunk & 1) * ECH;
        if (chunk + 1 < NCHUNKS) {
            prefetch_chunk(Eu + (uint32_t)((chunk + 1) & 1) * ECH, chunk + 1, tid);
            CP_WAIT(1);               // current buffer complete
        } else {
            CP_WAIT(0);
        }
        __syncthreads();

        // 4 n-tiles of 8 codes, 4 independent accumulator chains
        float ac0[4] = {0.f, 0.f, 0.f, 0.f}, ac1[4] = {0.f, 0.f, 0.f, 0.f};
        float ac2[4] = {0.f, 0.f, 0.f, 0.f}, ac3[4] = {0.f, 0.f, 0.f, 0.f};
        const uint32_t b01 = buf + brow4;              // tiles 0,1
        const uint32_t b23 = b01 + 16u * ESTRIDE;      // tiles 2,3
#pragma unroll
        for (int s = 0; s < KSTEPS; ++s) {
            uint32_t b00, b01r, b10, b11, b20, b21, b30, b31;
            ldmatrix_x4(b00, b01r, b10, b11, b01 + s * 32);
            ldmatrix_x4(b20, b21,  b30, b31, b23 + s * 32);
            mma4(ac0, ah[s], b00, b01r);
            mma4(ac1, ah[s], b10, b11);
            mma4(ac2, ah[s], b20, b21);
            mma4(ac3, ah[s], b30, b31);
        }
        const int cb = chunk * CCHUNK + (lane & 3) * 2;
        ins6(ac0[0], cb +  0, vA, ixA); ins6(ac0[1], cb +  1, vA, ixA);
        ins6(ac0[2], cb +  0, vB, ixB); ins6(ac0[3], cb +  1, vB, ixB);
        ins6(ac1[0], cb +  8, vA, ixA); ins6(ac1[1], cb +  9, vA, ixA);
        ins6(ac1[2], cb +  8, vB, ixB); ins6(ac1[3], cb +  9, vB, ixB);
        ins6(ac2[0], cb + 16, vA, ixA); ins6(ac2[1], cb + 17, vA, ixA);
        ins6(ac2[2], cb + 16, vB, ixB); ins6(ac2[3], cb + 17, vB, ixB);
        ins6(ac3[0], cb + 24, vA, ixA); ins6(ac3[1], cb + 25, vA, ixA);
        ins6(ac3[2], cb + 24, vB, ixB); ins6(ac3[3], cb + 25, vB, ixB);
        __syncthreads();              // done reading buf before it is refilled
    }

    // ---- no cross-lane merge: each lane stores its top-6 (24/row) ---------
    {
        int rA = w * 16 + (lane >> 2);
        int sl = (lane & 3) * 6;
#pragma unroll
        for (int j = 0; j < 6; ++j) {
            sCand[rA][sl + j]     = ixA[j];
            sCand[rA + 8][sl + j] = ixB[j];
        }
    }
    __syncthreads();

    // ---- Phase 2a: fp32 diff-form rescore of 24 cands -> row top-4 --------
    // 2 threads/row x 12 cands each; merge top-4 via partner shfl.
    float t4v[4] = {FLT_MAX, FLT_MAX, FLT_MAX, FLT_MAX};
    int   t4i[4] = {INT_MAX, INT_MAX, INT_MAX, INT_MAX};
    {
        int r = tid >> 1, half = tid & 1;
        const float4* x4 = reinterpret_cast<const float4*>(X + (size_t)(rowbase + r) * DDIM);
#pragma unroll 1
        for (int j = 0; j < 12; ++j) {
            int cand = sCand[r][half * 12 + j];
            const float4* ep = reinterpret_cast<const float4*>(E + (size_t)cand * DDIM);
            float dd = 0.0f;
#pragma unroll 4
            for (int k = 0; k < DDIM / 4; ++k) {
                float4 xv = x4[k], ev = ep[k];
                float d;
                d = xv.x - ev.x; dd += d * d;
                d = xv.y - ev.y; dd += d * d;
                d = xv.z - ev.z; dd += d * d;
                d = xv.w - ev.w; dd += d * d;
            }
            ins4min(dd, cand, t4v, t4i);
        }
#pragma unroll
        for (int j = 0; j < 4; ++j) {
            float ov = __shfl_xor_sync(0xffffffffu, t4v[j], 1);
            int   oi = __shfl_xor_sync(0xffffffffu, t4i[j], 1);
            ins4min(ov, oi, t4v, t4i);   // both partners -> identical top-4
        }
    }

    // ---- Phase 2b: exact fp64 rescore of top-4 (2 cands/thread) -----------
    {
        int r = tid >> 1, half = tid & 1;
        int cA = t4i[half];          // ranks {0,1}
        int cB = t4i[half + 2];      // ranks {2,3}
        const float4* x4 = reinterpret_cast<const float4*>(X + (size_t)(rowbase + r) * DDIM);
        const float4* ea = reinterpret_cast<const float4*>(E + (size_t)cA * DDIM);
        const float4* eb = reinterpret_cast<const float4*>(E + (size_t)cB * DDIM);
        double dA = 0.0, dB = 0.0;
#pragma unroll 4
        for (int j = 0; j < DDIM / 4; ++j) {
            float4 xv = x4[j], va = ea[j], vb = eb[j];
            double d;
            d = (double)xv.x - (double)va.x; dA += d * d;
            d = (double)xv.y - (double)va.y; dA += d * d;
            d = (double)xv.z - (double)va.z; dA += d * d;
            d = (double)xv.w - (double)va.w; dA += d * d;
            d = (double)xv.x - (double)vb.x; dB += d * d;
            d = (double)xv.y - (double)vb.y; dB += d * d;
            d = (double)xv.z - (double)vb.z; dB += d * d;
            d = (double)xv.w - (double)vb.w; dB += d * d;
        }
        double dmin = dA; int cmin = cA;
        if (dB < dmin || (dB == dmin && cB < cmin)) { dmin = dB; cmin = cB; }
        double od = __shfl_xor_sync(0xffffffffu, dmin, 1);
        int    oc = __shfl_xor_sync(0xffffffffu, cmin, 1);
        if (od < dmin || (od == dmin && oc < cmin)) { cmin = oc; }
        if (half == 0) sWin[r] = cmin;
    }
    __syncthreads();

    // ---- epilogue: gather + straight-through + loss (bit-exact to R2) -----
    float lsum = 0.0f;
    {
        const float4* xg = reinterpret_cast<const float4*>(X + (size_t)rowbase * DDIM);
        for (int i = tid; i < M_TILE * (DDIM / 4); i += THREADS) {
            int r = i >> 6, c4 = i & 63;
            int idx = sWin[r];
            float4 e = *reinterpret_cast<const float4*>(E + (size_t)idx * DDIM + c4 * 4);
            float4 x = xg[i];
            float4 d, q;
            d.x = e.x - x.x; d.y = e.y - x.y; d.z = e.z - x.z; d.w = e.w - x.w;
            q.x = x.x + d.x; q.y = x.y + d.y; q.z = x.z + d.z; q.w = x.w + d.w;
            lsum += d.x * d.x + d.y * d.y + d.z * d.z + d.w * d.w;
            *reinterpret_cast<float4*>(outQ + (size_t)(rowbase + r) * DDIM + c4 * 4) = q;
        }
    }
    if (tid < M_TILE) outIdx[rowbase + tid] = (float)sWin[tid];

#pragma unroll
    for (int s = 16; s >= 1; s >>= 1)
        lsum += __shfl_xor_sync(0xffffffffu, lsum, s);
    if (lane == 0) sRed[w] = lsum;
    __syncthreads();
    if (tid == 0) {
        float s = 0.0f;
#pragma unroll
        for (int i = 0; i < WARPS; ++i) s += sRed[i];
        atomicAdd(&g_loss_accum, (double)s);
    }
}

// ---------------------------------------------------------------------------
__global__ void vq_finalize(float* __restrict__ outLoss) {
    if (threadIdx.x == 0)
        *outLoss = (float)(g_loss_accum * (1.0 / (double)((size_t)NROWS * DDIM)));
}

// ---------------------------------------------------------------------------
extern "C" void kernel_launch(void* const* d_in, const int* in_sizes, int n_in,
                              void* d_out, int out_size) {
    (void)in_sizes; (void)n_in; (void)out_size;
    const float* X = (const float*)d_in[0];
    const float* E = (const float*)d_in[1];

    float* outQ    = (float*)d_out;
    float* outLoss = outQ + (size_t)NROWS * DDIM;   // 16777216
    float* outIdx  = outLoss + 1;                   // 16777217

    cudaFuncSetAttribute(vq_main_mma, cudaFuncAttributeMaxDynamicSharedMemorySize,
                         DYN_SMEM);

    vq_prep<<<KCODES / 8, 256>>>(E);
    vq_main_mma<<<NROWS / M_TILE, THREADS, DYN_SMEM>>>(X, E, outQ, outIdx);
    vq_finalize<<<1, 32>>>(outLoss);
}

// round 12
// speedup vs baseline: 4.9326x; 1.5076x over previous
#include <cuda_runtime.h>
#include <cuda_bf16.h>
#include <float.h>
#include <limits.h>
#include <stdint.h>

// VectorQuantizerEMA forward (eval mode).
//   d_in[0] = X [65536, 256] f32,  d_in[1] = E [1024, 256] f32
//   out (f32): [quantized_st 16777216 | loss 1 | indices 65536]
//
// Phase 1: SINGLE-PASS bf16 scoring GEMM on mma.sync m16n8k16 (native on
//   sm_103; fp16.f32 mma is ptxas-emulated ~13x slower -- measured R10/R11).
//   ||e||^2 folded via 2 augmented K-cols. Lane-local top-6 -> 24 disjoint
//   candidates/row. E chunks double-buffered via cp.async.
// Phase 2 (R12: warp-cooperative & COALESCED -- R11's per-lane rescore
//   splintered every warp load into 32 lines, ~900us):
//   warp-per-row, lanes split 256 dims; fp32 rescore of 24 cands -> top-2;
//   fp64 exact rescore of top-2 (R2-validated sufficiency).
// Epilogue: identical fp32 math to the reference (bit-exact).
//
// NOTE: harness compiles at compute_103 (no 'a'): tcgen05/TMEM unavailable.

#define NROWS    65536
#define DDIM     256
#define KAUG     272               // 256 + 16 (cols 256/257: -|e|^2/2 cascade)
#define KSTEPS   (KAUG / 16)       // 17
#define KCODES   1024
#define M_TILE   128
#define THREADS  256
#define WARPS    8
#define CCHUNK   32                // codes per smem chunk
#define NCHUNKS  (KCODES / CCHUNK) // 32
#define ESTRIDE  560               // bytes/row: 280 bf16 (272 used + pad)
#define X_BYTES  (M_TILE * ESTRIDE)       // 71680
#define ECH      (CCHUNK * ESTRIDE)       // 17920 per chunk
#define OFF_X    0
#define OFF_E    X_BYTES
#define DYN_SMEM (X_BYTES + 2 * ECH)      // 107520

__device__ double g_loss_accum;
__device__ __align__(16) unsigned char g_Ebf[KCODES * ESTRIDE];  // 573 KB

// ---------------------------------------------------------------------------
__device__ __forceinline__ uint32_t smem_u32(const void* p) {
    uint32_t a;
    asm("{ .reg .u64 t; cvta.to.shared.u64 t, %1; cvt.u32.u64 %0, t; }"
        : "=r"(a) : "l"(p));
    return a;
}
__device__ __forceinline__ void ldmatrix_x4(uint32_t& r0, uint32_t& r1,
                                            uint32_t& r2, uint32_t& r3,
                                            uint32_t addr) {
    asm volatile("ldmatrix.sync.aligned.m8n8.x4.shared.b16 {%0,%1,%2,%3}, [%4];"
                 : "=r"(r0), "=r"(r1), "=r"(r2), "=r"(r3) : "r"(addr));
}
__device__ __forceinline__ void mma4(float c[4], const uint32_t a[4],
                                     uint32_t b0, uint32_t b1) {
    asm volatile(
        "mma.sync.aligned.m16n8k16.row.col.f32.bf16.bf16.f32 "
        "{%0,%1,%2,%3}, {%4,%5,%6,%7}, {%8,%9}, {%0,%1,%2,%3};"
        : "+f"(c[0]), "+f"(c[1]), "+f"(c[2]), "+f"(c[3])
        : "r"(a[0]), "r"(a[1]), "r"(a[2]), "r"(a[3]), "r"(b0), "r"(b1));
}
#define CP16(dst, src) \
    asm volatile("cp.async.cg.shared.global [%0], [%1], 16;" \
                 :: "r"(dst), "l"(src) : "memory")
#define CP_COMMIT() asm volatile("cp.async.commit_group;" ::: "memory")
#define CP_WAIT(n)  asm volatile("cp.async.wait_group %0;" :: "n"(n) : "memory")

// sorted top-6 by score desc (constant-index nested ifs -> predicated
// selects, register resident; R8-proven pattern, NO loops/returns).
// Strict '>' only: in-lane codes ascend, so ties keep the earlier code.
__device__ __forceinline__ void ins6(float s, int c, float v[6], int ix[6]) {
    if (s > v[5]) {
        if (s > v[4]) {
            v[5] = v[4]; ix[5] = ix[4];
            if (s > v[3]) {
                v[4] = v[3]; ix[4] = ix[3];
                if (s > v[2]) {
                    v[3] = v[2]; ix[3] = ix[2];
                    if (s > v[1]) {
                        v[2] = v[1]; ix[2] = ix[1];
                        if (s > v[0]) {
                            v[1] = v[0]; ix[1] = ix[0]; v[0] = s; ix[0] = c;
                        } else { v[1] = s; ix[1] = c; }
                    } else { v[2] = s; ix[2] = c; }
                } else { v[3] = s; ix[3] = c; }
            } else { v[4] = s; ix[4] = c; }
        } else { v[5] = s; ix[5] = c; }
    }
}

// ---------------------------------------------------------------------------
// prep: E -> bf16 rows of 280 (272 used); aug cols 256/257 carry a 2-term
// bf16 cascade of -|e|^2/2 (residual ~5e-4 << score noise). One warp/code.
// ---------------------------------------------------------------------------
__global__ void vq_prep(const float* __restrict__ E) {
    const int w = threadIdx.x >> 5, lane = threadIdx.x & 31;
    const int code = blockIdx.x * 8 + w;
    if (blockIdx.x == 0 && threadIdx.x == 0) g_loss_accum = 0.0;

    const float4* e4 = reinterpret_cast<const float4*>(E + (size_t)code * DDIM);
    float4 va = e4[lane * 2], vb = e4[lane * 2 + 1];

    __nv_bfloat162 p0 = __floats2bfloat162_rn(va.x, va.y);
    __nv_bfloat162 p1 = __floats2bfloat162_rn(va.z, va.w);
    __nv_bfloat162 p2 = __floats2bfloat162_rn(vb.x, vb.y);
    __nv_bfloat162 p3 = __floats2bfloat162_rn(vb.z, vb.w);
    uint4 out;
    out.x = *reinterpret_cast<uint32_t*>(&p0);
    out.y = *reinterpret_cast<uint32_t*>(&p1);
    out.z = *reinterpret_cast<uint32_t*>(&p2);
    out.w = *reinterpret_cast<uint32_t*>(&p3);
    *reinterpret_cast<uint4*>(g_Ebf + (size_t)code * ESTRIDE + lane * 16) = out;

    double s = 0.0;
    s += (double)va.x * va.x; s += (double)va.y * va.y;
    s += (double)va.z * va.z; s += (double)va.w * va.w;
    s += (double)vb.x * vb.x; s += (double)vb.y * vb.y;
    s += (double)vb.z * vb.z; s += (double)vb.w * vb.w;
#pragma unroll
    for (int o = 16; o >= 1; o >>= 1)
        s += __shfl_xor_sync(0xffffffffu, s, o);

    if (lane == 0) {
        double d = -0.5 * s;
        __nv_bfloat16 h1 = __float2bfloat16_rn((float)d);
        d -= (double)__bfloat162float(h1);
        __nv_bfloat16 h2 = __float2bfloat16_rn((float)d);
        uint32_t w0 = (uint32_t)*reinterpret_cast<unsigned short*>(&h1) |
                      ((uint32_t)*reinterpret_cast<unsigned short*>(&h2) << 16);
        unsigned char* b = g_Ebf + (size_t)code * ESTRIDE + 512;
        *reinterpret_cast<uint4*>(b +  0) = make_uint4(w0, 0u, 0u, 0u);
        *reinterpret_cast<uint4*>(b + 16) = make_uint4(0u, 0u, 0u, 0u);
        *reinterpret_cast<uint4*>(b + 32) = make_uint4(0u, 0u, 0u, 0u);
    }
}

// ---------------------------------------------------------------------------
__device__ __forceinline__ void prefetch_chunk(uint32_t dst, int chunk, int tid) {
    const unsigned char* src = g_Ebf + (size_t)chunk * ECH;
#pragma unroll 1
    for (int i = tid; i < ECH / 16; i += THREADS)
        CP16(dst + (uint32_t)i * 16u, src + (size_t)i * 16);
    CP_COMMIT();
}

// ---------------------------------------------------------------------------
// main: 512 CTAs x 256 threads (8 warps); warp w owns rows w*16 .. w*16+15.
// ---------------------------------------------------------------------------
__global__ __launch_bounds__(THREADS, 1)
void vq_main_mma(const float* __restrict__ X, const float* __restrict__ E,
                 float* __restrict__ outQ, float* __restrict__ outIdx) {
    extern __shared__ __align__(16) unsigned char sm[];
    __shared__ int   sCand[M_TILE][24];
    __shared__ int   sWin[M_TILE];
    __shared__ float sRed[WARPS];

    const int tid  = threadIdx.x;
    const int w    = tid >> 5;
    const int lane = tid & 31;
    const int rowbase = blockIdx.x * M_TILE;

    const uint32_t sm_u = smem_u32(sm);
    const uint32_t Eu   = sm_u + OFF_E;

    // kick off E chunk 0 prefetch immediately (disjoint from X staging)
    prefetch_chunk(Eu, 0, tid);

    // ---- stage X tile: f32 -> bf16 rows of 280 + aug cols (1.0, 1.0) ------
    for (int i = tid; i < M_TILE * 3; i += THREADS) {
        int r = i / 3, part = i % 3;
        uint4 val = (part == 0) ? make_uint4(0x3F803F80u, 0u, 0u, 0u)
                                : make_uint4(0u, 0u, 0u, 0u);
        *reinterpret_cast<uint4*>(sm + OFF_X + r * ESTRIDE + 512 + part * 16) = val;
    }
    {
        const float4* xg = reinterpret_cast<const float4*>(X + (size_t)rowbase * DDIM);
        for (int i = tid; i < M_TILE * (DDIM / 4); i += THREADS) {
            int r = i >> 6, c4 = i & 63;
            float4 v = xg[i];
            __nv_bfloat162 q0 = __floats2bfloat162_rn(v.x, v.y);
            __nv_bfloat162 q1 = __floats2bfloat162_rn(v.z, v.w);
            uint2 o;
            o.x = *reinterpret_cast<uint32_t*>(&q0);
            o.y = *reinterpret_cast<uint32_t*>(&q1);
            *reinterpret_cast<uint2*>(sm + OFF_X + r * ESTRIDE + c4 * 8) = o;
        }
    }
    __syncthreads();

    // ---- register-resident A fragments (17 ksteps x 4 regs) ---------------
    uint32_t ah[KSTEPS][4];
    {
        uint32_t off = (uint32_t)(w * 16 + (lane & 15)) * ESTRIDE +
                       (uint32_t)((lane >> 4) * 16);
#pragma unroll
        for (int s = 0; s < KSTEPS; ++s)
            ldmatrix_x4(ah[s][0], ah[s][1], ah[s][2], ah[s][3],
                        sm_u + OFF_X + off + s * 32);
    }

    // ---- score all codes; lane-local top-6 for rows (A, A+8) --------------
    float vA[6] = {-FLT_MAX, -FLT_MAX, -FLT_MAX, -FLT_MAX, -FLT_MAX, -FLT_MAX};
    float vB[6] = {-FLT_MAX, -FLT_MAX, -FLT_MAX, -FLT_MAX, -FLT_MAX, -FLT_MAX};
    int ixA[6] = {INT_MAX, INT_MAX, INT_MAX, INT_MAX, INT_MAX, INT_MAX};
    int ixB[6] = {INT_MAX, INT_MAX, INT_MAX, INT_MAX, INT_MAX, INT_MAX};

    // ldmatrix.x4 B address (validated R10/R11): matrices {tile k0-7,
    // tile k8-15, tile+1 k0-7, tile+1 k8-15}.
    const uint32_t brow4 = (uint32_t)(lane & 7) * ESTRIDE +
                           (uint32_t)(((lane >> 3) & 1) * 16) +
                           (uint32_t)((lane >> 4) * 8) * ESTRIDE;

    for (int chunk = 0; chunk < NCHUNKS; ++chunk) {
        const uint32_t buf = Eu + (uint32_t)(chunk & 1) * ECH;
        if (chunk + 1 < NCHUNKS) {
            prefetch_chunk(Eu + (uint32_t)((chunk + 1) & 1) * ECH, chunk + 1, tid);
            CP_WAIT(1);               // current buffer complete
        } else {
            CP_WAIT(0);
        }
        __syncthreads();

        // 4 n-tiles of 8 codes, 4 independent accumulator chains
        float ac0[4] = {0.f, 0.f, 0.f, 0.f}, ac1[4] = {0.f, 0.f, 0.f, 0.f};
        float ac2[4] = {0.f, 0.f, 0.f, 0.f}, ac3[4] = {0.f, 0.f, 0.f, 0.f};
        const uint32_t b01 = buf + brow4;              // tiles 0,1
        const uint32_t b23 = b01 + 16u * ESTRIDE;      // tiles 2,3
#pragma unroll
        for (int s = 0; s < KSTEPS; ++s) {
            uint32_t b00, b01r, b10, b11, b20, b21, b30, b31;
            ldmatrix_x4(b00, b01r, b10, b11, b01 + s * 32);
            ldmatrix_x4(b20, b21,  b30, b31, b23 + s * 32);
            mma4(ac0, ah[s], b00, b01r);
            mma4(ac1, ah[s], b10, b11);
            mma4(ac2, ah[s], b20, b21);
            mma4(ac3, ah[s], b30, b31);
        }
        const int cb = chunk * CCHUNK + (lane & 3) * 2;
        ins6(ac0[0], cb +  0, vA, ixA); ins6(ac0[1], cb +  1, vA, ixA);
        ins6(ac0[2], cb +  0, vB, ixB); ins6(ac0[3], cb +  1, vB, ixB);
        ins6(ac1[0], cb +  8, vA, ixA); ins6(ac1[1], cb +  9, vA, ixA);
        ins6(ac1[2], cb +  8, vB, ixB); ins6(ac1[3], cb +  9, vB, ixB);
        ins6(ac2[0], cb + 16, vA, ixA); ins6(ac2[1], cb + 17, vA, ixA);
        ins6(ac2[2], cb + 16, vB, ixB); ins6(ac2[3], cb + 17, vB, ixB);
        ins6(ac3[0], cb + 24, vA, ixA); ins6(ac3[1], cb + 25, vA, ixA);
        ins6(ac3[2], cb + 24, vB, ixB); ins6(ac3[3], cb + 25, vB, ixB);
        __syncthreads();              // done reading buf before it is refilled
    }

    // ---- no cross-lane merge: each lane stores its top-6 (24/row) ---------
    {
        int rA = w * 16 + (lane >> 2);
        int sl = (lane & 3) * 6;
#pragma unroll
        for (int j = 0; j < 6; ++j) {
            sCand[rA][sl + j]     = ixA[j];
            sCand[rA + 8][sl + j] = ixB[j];
        }
    }
    __syncthreads();

    // ---- Phase 2: warp-per-row COALESCED rescore --------------------------
    // Lanes split 256 dims (8 floats each). fp32 pass over 24 cands -> top-2,
    // then exact fp64 on the 2 finalists. All loads coalesced warp-wide.
    for (int rr = 0; rr < M_TILE / WARPS; ++rr) {
        const int r = w * (M_TILE / WARPS) + rr;
        const float4* x4 = reinterpret_cast<const float4*>(
            X + (size_t)(rowbase + r) * DDIM);
        const float4 xa = x4[lane * 2], xb = x4[lane * 2 + 1];

        float v1 = FLT_MAX, v2 = FLT_MAX;
        int   i1 = INT_MAX, i2 = INT_MAX;
#pragma unroll 2
        for (int c = 0; c < 24; ++c) {
            const int cand = sCand[r][c];           // smem broadcast
            const float4* e4 = reinterpret_cast<const float4*>(
                E + (size_t)cand * DDIM);
            const float4 ea = e4[lane * 2], eb = e4[lane * 2 + 1];
            float d, dd = 0.0f;
            d = xa.x - ea.x; dd += d * d;  d = xa.y - ea.y; dd += d * d;
            d = xa.z - ea.z; dd += d * d;  d = xa.w - ea.w; dd += d * d;
            d = xb.x - eb.x; dd += d * d;  d = xb.y - eb.y; dd += d * d;
            d = xb.z - eb.z; dd += d * d;  d = xb.w - eb.w; dd += d * d;
#pragma unroll
            for (int o = 16; o >= 1; o >>= 1)
                dd += __shfl_xor_sync(0xffffffffu, dd, o);
            // all lanes hold identical dd -> identical top-2 state
            if (dd < v1 || (dd == v1 && cand < i1)) {
                v2 = v1; i2 = i1; v1 = dd; i1 = cand;
            } else if (dd < v2 || (dd == v2 && cand < i2)) {
                v2 = dd; i2 = cand;
            }
        }

        // exact fp64 on the two finalists (coalesced, warp-reduced)
        const float4* ea4 = reinterpret_cast<const float4*>(E + (size_t)i1 * DDIM);
        const float4* eb4 = reinterpret_cast<const float4*>(E + (size_t)i2 * DDIM);
        const float4 a0 = ea4[lane * 2], a1 = ea4[lane * 2 + 1];
        const float4 b0 = eb4[lane * 2], b1 = eb4[lane * 2 + 1];
        double d, dA = 0.0, dB = 0.0;
        d = (double)xa.x - (double)a0.x; dA += d * d;
        d = (double)xa.y - (double)a0.y; dA += d * d;
        d = (double)xa.z - (double)a0.z; dA += d * d;
        d = (double)xa.w - (double)a0.w; dA += d * d;
        d = (double)xb.x - (double)a1.x; dA += d * d;
        d = (double)xb.y - (double)a1.y; dA += d * d;
        d = (double)xb.z - (double)a1.z; dA += d * d;
        d = (double)xb.w - (double)a1.w; dA += d * d;
        d = (double)xa.x - (double)b0.x; dB += d * d;
        d = (double)xa.y - (double)b0.y; dB += d * d;
        d = (double)xa.z - (double)b0.z; dB += d * d;
        d = (double)xa.w - (double)b0.w; dB += d * d;
        d = (double)xb.x - (double)b1.x; dB += d * d;
        d = (double)xb.y - (double)b1.y; dB += d * d;
        d = (double)xb.z - (double)b1.z; dB += d * d;
        d = (double)xb.w - (double)b1.w; dB += d * d;
#pragma unroll
        for (int o = 16; o >= 1; o >>= 1) {
            dA += __shfl_xor_sync(0xffffffffu, dA, o);
            dB += __shfl_xor_sync(0xffffffffu, dB, o);
        }
        int win = (dA < dB || (dA == dB && i1 < i2)) ? i1 : i2;
        if (lane == 0) sWin[r] = win;
    }
    __syncthreads();

    // ---- epilogue: gather + straight-through + loss (bit-exact to R2) -----
    float lsum = 0.0f;
    {
        const float4* xg = reinterpret_cast<const float4*>(X + (size_t)rowbase * DDIM);
        for (int i = tid; i < M_TILE * (DDIM / 4); i += THREADS) {
            int r = i >> 6, c4 = i & 63;
            int idx = sWin[r];
            float4 e = *reinterpret_cast<const float4*>(E + (size_t)idx * DDIM + c4 * 4);
            float4 x = xg[i];
            float4 d, q;
            d.x = e.x - x.x; d.y = e.y - x.y; d.z = e.z - x.z; d.w = e.w - x.w;
            q.x = x.x + d.x; q.y = x.y + d.y; q.z = x.z + d.z; q.w = x.w + d.w;
            lsum += d.x * d.x + d.y * d.y + d.z * d.z + d.w * d.w;
            *reinterpret_cast<float4*>(outQ + (size_t)(rowbase + r) * DDIM + c4 * 4) = q;
        }
    }
    if (tid < M_TILE) outIdx[rowbase + tid] = (float)sWin[tid];

#pragma unroll
    for (int s = 16; s >= 1; s >>= 1)
        lsum += __shfl_xor_sync(0xffffffffu, lsum, s);
    if (lane == 0) sRed[w] = lsum;
    __syncthreads();
    if (tid == 0) {
        float s = 0.0f;
#pragma unroll
        for (int i = 0; i < WARPS; ++i) s += sRed[i];
        atomicAdd(&g_loss_accum, (double)s);
    }
}

// ---------------------------------------------------------------------------
__global__ void vq_finalize(float* __restrict__ outLoss) {
    if (threadIdx.x == 0)
        *outLoss = (float)(g_loss_accum * (1.0 / (double)((size_t)NROWS * DDIM)));
}

// ---------------------------------------------------------------------------
extern "C" void kernel_launch(void* const* d_in, const int* in_sizes, int n_in,
                              void* d_out, int out_size) {
    (void)in_sizes; (void)n_in; (void)out_size;
    const float* X = (const float*)d_in[0];
    const float* E = (const float*)d_in[1];

    float* outQ    = (float*)d_out;
    float* outLoss = outQ + (size_t)NROWS * DDIM;   // 16777216
    float* outIdx  = outLoss + 1;                   // 16777217

    cudaFuncSetAttribute(vq_main_mma, cudaFuncAttributeMaxDynamicSharedMemorySize,
                         DYN_SMEM);

    vq_prep<<<KCODES / 8, 256>>>(E);
    vq_main_mma<<<NROWS / M_TILE, THREADS, DYN_SMEM>>>(X, E, outQ, outIdx);
    vq_finalize<<<1, 32>>>(outLoss);
}

// round 13
// speedup vs baseline: 5.0080x; 1.0153x over previous
#include <cuda_runtime.h>
#include <cuda_bf16.h>
#include <float.h>
#include <limits.h>
#include <stdint.h>

// VectorQuantizerEMA forward (eval mode).
//   d_in[0] = X [65536, 256] f32,  d_in[1] = E [1024, 256] f32
//   out (f32): [quantized_st 16777216 | loss 1 | indices 65536]
//
// Phase 1: SINGLE-PASS bf16 scoring GEMM on mma.sync m16n8k16 (native on
//   sm_103). ||e||^2 folded via 2 augmented K-cols. Lane-local top-6 -> 24
//   disjoint candidates/row.
//   R13: per-chunk fixed cost ~12K cyc measured constant across 3x work
//   (R8 vs R12) -> amortize it: CCHUNK 32->128 (8 chunks, double-buffered)
//   + 2-stage ldmatrix software pipeline.
// Phase 2: warp-per-row COALESCED fp32 rescore of 24 -> top-2; exact fp64
//   on the 2 finalists (R12-validated).
// Epilogue: identical fp32 math to the reference (bit-exact).
//
// NOTE: harness compiles at compute_103 (no 'a'): tcgen05/TMEM unavailable;
// fp16.f32 mma is ptxas-emulated ~13x slower than bf16 (measured R10/R11).

#define NROWS    65536
#define DDIM     256
#define KAUG     272               // 256 + 16 (cols 256/257: -|e|^2/2 cascade)
#define KSTEPS   (KAUG / 16)       // 17
#define KCODES   1024
#define M_TILE   128
#define THREADS  256
#define WARPS    8
#define CCHUNK   128               // codes per smem chunk (R13: was 32)
#define NCHUNKS  (KCODES / CCHUNK) // 8
#define NGROUPS  4                 // 4 groups of 32 codes per chunk
#define ESTRIDE  560               // bytes/row: 280 bf16 (272 used + pad)
#define X_BYTES  (M_TILE * ESTRIDE)       // 71680
#define ECH      (CCHUNK * ESTRIDE)       // 71680 per chunk
#define OFF_X    0
#define OFF_E    X_BYTES
#define DYN_SMEM (X_BYTES + 2 * ECH)      // 215040 (+ ~12.8KB static < 232448)

__device__ double g_loss_accum;
__device__ __align__(16) unsigned char g_Ebf[KCODES * ESTRIDE];  // 573 KB

// ---------------------------------------------------------------------------
__device__ __forceinline__ uint32_t smem_u32(const void* p) {
    uint32_t a;
    asm("{ .reg .u64 t; cvta.to.shared.u64 t, %1; cvt.u32.u64 %0, t; }"
        : "=r"(a) : "l"(p));
    return a;
}
__device__ __forceinline__ void ldmatrix_x4(uint32_t& r0, uint32_t& r1,
                                            uint32_t& r2, uint32_t& r3,
                                            uint32_t addr) {
    asm volatile("ldmatrix.sync.aligned.m8n8.x4.shared.b16 {%0,%1,%2,%3}, [%4];"
                 : "=r"(r0), "=r"(r1), "=r"(r2), "=r"(r3) : "r"(addr));
}
__device__ __forceinline__ void mma4(float c[4], const uint32_t a[4],
                                     uint32_t b0, uint32_t b1) {
    asm volatile(
        "mma.sync.aligned.m16n8k16.row.col.f32.bf16.bf16.f32 "
        "{%0,%1,%2,%3}, {%4,%5,%6,%7}, {%8,%9}, {%0,%1,%2,%3};"
        : "+f"(c[0]), "+f"(c[1]), "+f"(c[2]), "+f"(c[3])
        : "r"(a[0]), "r"(a[1]), "r"(a[2]), "r"(a[3]), "r"(b0), "r"(b1));
}
#define CP16(dst, src) \
    asm volatile("cp.async.cg.shared.global [%0], [%1], 16;" \
                 :: "r"(dst), "l"(src) : "memory")
#define CP_COMMIT() asm volatile("cp.async.commit_group;" ::: "memory")
#define CP_WAIT(n)  asm volatile("cp.async.wait_group %0;" :: "n"(n) : "memory")

// sorted top-6 by score desc (constant-index nested ifs -> predicated
// selects, register resident; NO loops/returns). Strict '>' only: in-lane
// codes ascend, so ties keep the earlier code.
__device__ __forceinline__ void ins6(float s, int c, float v[6], int ix[6]) {
    if (s > v[5]) {
        if (s > v[4]) {
            v[5] = v[4]; ix[5] = ix[4];
            if (s > v[3]) {
                v[4] = v[3]; ix[4] = ix[3];
                if (s > v[2]) {
                    v[3] = v[2]; ix[3] = ix[2];
                    if (s > v[1]) {
                        v[2] = v[1]; ix[2] = ix[1];
                        if (s > v[0]) {
                            v[1] = v[0]; ix[1] = ix[0]; v[0] = s; ix[0] = c;
                        } else { v[1] = s; ix[1] = c; }
                    } else { v[2] = s; ix[2] = c; }
                } else { v[3] = s; ix[3] = c; }
            } else { v[4] = s; ix[4] = c; }
        } else { v[5] = s; ix[5] = c; }
    }
}

// ---------------------------------------------------------------------------
// prep: E -> bf16 rows of 280 (272 used); aug cols 256/257 carry a 2-term
// bf16 cascade of -|e|^2/2. One warp per code. (Layout is code-major, so
// a 128-code chunk is a contiguous ECH-byte span -- prefetch unchanged.)
// ---------------------------------------------------------------------------
__global__ void vq_prep(const float* __restrict__ E) {
    const int w = threadIdx.x >> 5, lane = threadIdx.x & 31;
    const int code = blockIdx.x * 8 + w;
    if (blockIdx.x == 0 && threadIdx.x == 0) g_loss_accum = 0.0;

    const float4* e4 = reinterpret_cast<const float4*>(E + (size_t)code * DDIM);
    float4 va = e4[lane * 2], vb = e4[lane * 2 + 1];

    __nv_bfloat162 p0 = __floats2bfloat162_rn(va.x, va.y);
    __nv_bfloat162 p1 = __floats2bfloat162_rn(va.z, va.w);
    __nv_bfloat162 p2 = __floats2bfloat162_rn(vb.x, vb.y);
    __nv_bfloat162 p3 = __floats2bfloat162_rn(vb.z, vb.w);
    uint4 out;
    out.x = *reinterpret_cast<uint32_t*>(&p0);
    out.y = *reinterpret_cast<uint32_t*>(&p1);
    out.z = *reinterpret_cast<uint32_t*>(&p2);
    out.w = *reinterpret_cast<uint32_t*>(&p3);
    *reinterpret_cast<uint4*>(g_Ebf + (size_t)code * ESTRIDE + lane * 16) = out;

    double s = 0.0;
    s += (double)va.x * va.x; s += (double)va.y * va.y;
    s += (double)va.z * va.z; s += (double)va.w * va.w;
    s += (double)vb.x * vb.x; s += (double)vb.y * vb.y;
    s += (double)vb.z * vb.z; s += (double)vb.w * vb.w;
#pragma unroll
    for (int o = 16; o >= 1; o >>= 1)
        s += __shfl_xor_sync(0xffffffffu, s, o);

    if (lane == 0) {
        double d = -0.5 * s;
        __nv_bfloat16 h1 = __float2bfloat16_rn((float)d);
        d -= (double)__bfloat162float(h1);
        __nv_bfloat16 h2 = __float2bfloat16_rn((float)d);
        uint32_t w0 = (uint32_t)*reinterpret_cast<unsigned short*>(&h1) |
                      ((uint32_t)*reinterpret_cast<unsigned short*>(&h2) << 16);
        unsigned char* b = g_Ebf + (size_t)code * ESTRIDE + 512;
        *reinterpret_cast<uint4*>(b +  0) = make_uint4(w0, 0u, 0u, 0u);
        *reinterpret_cast<uint4*>(b + 16) = make_uint4(0u, 0u, 0u, 0u);
        *reinterpret_cast<uint4*>(b + 32) = make_uint4(0u, 0u, 0u, 0u);
    }
}

// ---------------------------------------------------------------------------
__device__ __forceinline__ void prefetch_chunk(uint32_t dst, int chunk, int tid) {
    const unsigned char* src = g_Ebf + (size_t)chunk * ECH;
#pragma unroll 1
    for (int i = tid; i < ECH / 16; i += THREADS)
        CP16(dst + (uint32_t)i * 16u, src + (size_t)i * 16);
    CP_COMMIT();
}

// ---------------------------------------------------------------------------
// main: 512 CTAs x 256 threads (8 warps); warp w owns rows w*16 .. w*16+15.
// ---------------------------------------------------------------------------
__global__ __launch_bounds__(THREADS, 1)
void vq_main_mma(const float* __restrict__ X, const float* __restrict__ E,
                 float* __restrict__ outQ, float* __restrict__ outIdx) {
    extern __shared__ __align__(16) unsigned char sm[];
    __shared__ int   sCand[M_TILE][24];
    __shared__ int   sWin[M_TILE];
    __shared__ float sRed[WARPS];

    const int tid  = threadIdx.x;
    const int w    = tid >> 5;
    const int lane = tid & 31;
    const int rowbase = blockIdx.x * M_TILE;

    const uint32_t sm_u = smem_u32(sm);
    const uint32_t Eu   = sm_u + OFF_E;

    // kick off E chunk 0 prefetch immediately (disjoint from X staging)
    prefetch_chunk(Eu, 0, tid);

    // ---- stage X tile: f32 -> bf16 rows of 280 + aug cols (1.0, 1.0) ------
    for (int i = tid; i < M_TILE * 3; i += THREADS) {
        int r = i / 3, part = i % 3;
        uint4 val = (part == 0) ? make_uint4(0x3F803F80u, 0u, 0u, 0u)
                                : make_uint4(0u, 0u, 0u, 0u);
        *reinterpret_cast<uint4*>(sm + OFF_X + r * ESTRIDE + 512 + part * 16) = val;
    }
    {
        const float4* xg = reinterpret_cast<const float4*>(X + (size_t)rowbase * DDIM);
        for (int i = tid; i < M_TILE * (DDIM / 4); i += THREADS) {
            int r = i >> 6, c4 = i & 63;
            float4 v = xg[i];
            __nv_bfloat162 q0 = __floats2bfloat162_rn(v.x, v.y);
            __nv_bfloat162 q1 = __floats2bfloat162_rn(v.z, v.w);
            uint2 o;
            o.x = *reinterpret_cast<uint32_t*>(&q0);
            o.y = *reinterpret_cast<uint32_t*>(&q1);
            *reinterpret_cast<uint2*>(sm + OFF_X + r * ESTRIDE + c4 * 8) = o;
        }
    }
    __syncthreads();

    // ---- register-resident A fragments (17 ksteps x 4 regs) ---------------
    uint32_t ah[KSTEPS][4];
    {
        uint32_t off = (uint32_t)(w * 16 + (lane & 15)) * ESTRIDE +
                       (uint32_t)((lane >> 4) * 16);
#pragma unroll
        for (int s = 0; s < KSTEPS; ++s)
            ldmatrix_x4(ah[s][0], ah[s][1], ah[s][2], ah[s][3],
                        sm_u + OFF_X + off + s * 32);
    }

    // ---- score all codes; lane-local top-6 for rows (A, A+8) --------------
    float vA[6] = {-FLT_MAX, -FLT_MAX, -FLT_MAX, -FLT_MAX, -FLT_MAX, -FLT_MAX};
    float vB[6] = {-FLT_MAX, -FLT_MAX, -FLT_MAX, -FLT_MAX, -FLT_MAX, -FLT_MAX};
    int ixA[6] = {INT_MAX, INT_MAX, INT_MAX, INT_MAX, INT_MAX, INT_MAX};
    int ixB[6] = {INT_MAX, INT_MAX, INT_MAX, INT_MAX, INT_MAX, INT_MAX};

    // ldmatrix.x4 B address (validated R10-R12): matrices {tile k0-7,
    // tile k8-15, tile+1 k0-7, tile+1 k8-15}.
    const uint32_t brow4 = (uint32_t)(lane & 7) * ESTRIDE +
                           (uint32_t)(((lane >> 3) & 1) * 16) +
                           (uint32_t)((lane >> 4) * 8) * ESTRIDE;

    for (int chunk = 0; chunk < NCHUNKS; ++chunk) {
        const uint32_t buf = Eu + (uint32_t)(chunk & 1) * ECH;
        if (chunk + 1 < NCHUNKS) {
            prefetch_chunk(Eu + (uint32_t)((chunk + 1) & 1) * ECH, chunk + 1, tid);
            CP_WAIT(1);               // current buffer complete
        } else {
            CP_WAIT(0);
        }
        __syncthreads();

        // 4 groups x (4 n-tiles of 8 codes); 2-stage ldmatrix pipeline
#pragma unroll
        for (int g = 0; g < NGROUPS; ++g) {
            float ac0[4] = {0.f, 0.f, 0.f, 0.f}, ac1[4] = {0.f, 0.f, 0.f, 0.f};
            float ac2[4] = {0.f, 0.f, 0.f, 0.f}, ac3[4] = {0.f, 0.f, 0.f, 0.f};
            const uint32_t b01 = buf + brow4 + (uint32_t)(g * 32) * ESTRIDE;
            const uint32_t b23 = b01 + 16u * ESTRIDE;

            uint32_t c00, c01, c10, c11, c20, c21, c30, c31;   // current step
            ldmatrix_x4(c00, c01, c10, c11, b01);
            ldmatrix_x4(c20, c21, c30, c31, b23);
#pragma unroll
            for (int s = 0; s < KSTEPS; ++s) {
                uint32_t n00, n01, n10, n11, n20, n21, n30, n31;
                if (s + 1 < KSTEPS) {
                    ldmatrix_x4(n00, n01, n10, n11, b01 + (s + 1) * 32);
                    ldmatrix_x4(n20, n21, n30, n31, b23 + (s + 1) * 32);
                }
                mma4(ac0, ah[s], c00, c01);
                mma4(ac1, ah[s], c10, c11);
                mma4(ac2, ah[s], c20, c21);
                mma4(ac3, ah[s], c30, c31);
                if (s + 1 < KSTEPS) {
                    c00 = n00; c01 = n01; c10 = n10; c11 = n11;
                    c20 = n20; c21 = n21; c30 = n30; c31 = n31;
                }
            }
            const int cb = chunk * CCHUNK + g * 32 + (lane & 3) * 2;
            ins6(ac0[0], cb +  0, vA, ixA); ins6(ac0[1], cb +  1, vA, ixA);
            ins6(ac0[2], cb +  0, vB, ixB); ins6(ac0[3], cb +  1, vB, ixB);
            ins6(ac1[0], cb +  8, vA, ixA); ins6(ac1[1], cb +  9, vA, ixA);
            ins6(ac1[2], cb +  8, vB, ixB); ins6(ac1[3], cb +  9, vB, ixB);
            ins6(ac2[0], cb + 16, vA, ixA); ins6(ac2[1], cb + 17, vA, ixA);
            ins6(ac2[2], cb + 16, vB, ixB); ins6(ac2[3], cb + 17, vB, ixB);
            ins6(ac3[0], cb + 24, vA, ixA); ins6(ac3[1], cb + 25, vA, ixA);
            ins6(ac3[2], cb + 24, vB, ixB); ins6(ac3[3], cb + 25, vB, ixB);
        }
        __syncthreads();              // done reading buf before it is refilled
    }

    // ---- no cross-lane merge: each lane stores its top-6 (24/row) ---------
    {
        int rA = w * 16 + (lane >> 2);
        int sl = (lane & 3) * 6;
#pragma unroll
        for (int j = 0; j < 6; ++j) {
            sCand[rA][sl + j]     = ixA[j];
            sCand[rA + 8][sl + j] = ixB[j];
        }
    }
    __syncthreads();

    // ---- Phase 2: warp-per-row COALESCED rescore (R12-validated) ----------
    for (int rr = 0; rr < M_TILE / WARPS; ++rr) {
        const int r = w * (M_TILE / WARPS) + rr;
        const float4* x4 = reinterpret_cast<const float4*>(
            X + (size_t)(rowbase + r) * DDIM);
        const float4 xa = x4[lane * 2], xb = x4[lane * 2 + 1];

        float v1 = FLT_MAX, v2 = FLT_MAX;
        int   i1 = INT_MAX, i2 = INT_MAX;
#pragma unroll 2
        for (int c = 0; c < 24; ++c) {
            const int cand = sCand[r][c];           // smem broadcast
            const float4* e4 = reinterpret_cast<const float4*>(
                E + (size_t)cand * DDIM);
            const float4 ea = e4[lane * 2], eb = e4[lane * 2 + 1];
            float d, dd = 0.0f;
            d = xa.x - ea.x; dd += d * d;  d = xa.y - ea.y; dd += d * d;
            d = xa.z - ea.z; dd += d * d;  d = xa.w - ea.w; dd += d * d;
            d = xb.x - eb.x; dd += d * d;  d = xb.y - eb.y; dd += d * d;
            d = xb.z - eb.z; dd += d * d;  d = xb.w - eb.w; dd += d * d;
#pragma unroll
            for (int o = 16; o >= 1; o >>= 1)
                dd += __shfl_xor_sync(0xffffffffu, dd, o);
            if (dd < v1 || (dd == v1 && cand < i1)) {
                v2 = v1; i2 = i1; v1 = dd; i1 = cand;
            } else if (dd < v2 || (dd == v2 && cand < i2)) {
                v2 = dd; i2 = cand;
            }
        }

        // exact fp64 on the two finalists (coalesced, warp-reduced)
        const float4* ea4 = reinterpret_cast<const float4*>(E + (size_t)i1 * DDIM);
        const float4* eb4 = reinterpret_cast<const float4*>(E + (size_t)i2 * DDIM);
        const float4 a0 = ea4[lane * 2], a1 = ea4[lane * 2 + 1];
        const float4 b0 = eb4[lane * 2], b1 = eb4[lane * 2 + 1];
        double d, dA = 0.0, dB = 0.0;
        d = (double)xa.x - (double)a0.x; dA += d * d;
        d = (double)xa.y - (double)a0.y; dA += d * d;
        d = (double)xa.z - (double)a0.z; dA += d * d;
        d = (double)xa.w - (double)a0.w; dA += d * d;
        d = (double)xb.x - (double)a1.x; dA += d * d;
        d = (double)xb.y - (double)a1.y; dA += d * d;
        d = (double)xb.z - (double)a1.z; dA += d * d;
        d = (double)xb.w - (double)a1.w; dA += d * d;
        d = (double)xa.x - (double)b0.x; dB += d * d;
        d = (double)xa.y - (double)b0.y; dB += d * d;
        d = (double)xa.z - (double)b0.z; dB += d * d;
        d = (double)xa.w - (double)b0.w; dB += d * d;
        d = (double)xb.x - (double)b1.x; dB += d * d;
        d = (double)xb.y - (double)b1.y; dB += d * d;
        d = (double)xb.z - (double)b1.z; dB += d * d;
        d = (double)xb.w - (double)b1.w; dB += d * d;
#pragma unroll
        for (int o = 16; o >= 1; o >>= 1) {
            dA += __shfl_xor_sync(0xffffffffu, dA, o);
            dB += __shfl_xor_sync(0xffffffffu, dB, o);
        }
        int win = (dA < dB || (dA == dB && i1 < i2)) ? i1 : i2;
        if (lane == 0) sWin[r] = win;
    }
    __syncthreads();

    // ---- epilogue: gather + straight-through + loss (bit-exact to R2) -----
    float lsum = 0.0f;
    {
        const float4* xg = reinterpret_cast<const float4*>(X + (size_t)rowbase * DDIM);
        for (int i = tid; i < M_TILE * (DDIM / 4); i += THREADS) {
            int r = i >> 6, c4 = i & 63;
            int idx = sWin[r];
            float4 e = *reinterpret_cast<const float4*>(E + (size_t)idx * DDIM + c4 * 4);
            float4 x = xg[i];
            float4 d, q;
            d.x = e.x - x.x; d.y = e.y - x.y; d.z = e.z - x.z; d.w = e.w - x.w;
            q.x = x.x + d.x; q.y = x.y + d.y; q.z = x.z + d.z; q.w = x.w + d.w;
            lsum += d.x * d.x + d.y * d.y + d.z * d.z + d.w * d.w;
            *reinterpret_cast<float4*>(outQ + (size_t)(rowbase + r) * DDIM + c4 * 4) = q;
        }
    }
    if (tid < M_TILE) outIdx[rowbase + tid] = (float)sWin[tid];

#pragma unroll
    for (int s = 16; s >= 1; s >>= 1)
        lsum += __shfl_xor_sync(0xffffffffu, lsum, s);
    if (lane == 0) sRed[w] = lsum;
    __syncthreads();
    if (tid == 0) {
        float s = 0.0f;
#pragma unroll
        for (int i = 0; i < WARPS; ++i) s += sRed[i];
        atomicAdd(&g_loss_accum, (double)s);
    }
}

// ---------------------------------------------------------------------------
__global__ void vq_finalize(float* __restrict__ outLoss) {
    if (threadIdx.x == 0)
        *outLoss = (float)(g_loss_accum * (1.0 / (double)((size_t)NROWS * DDIM)));
}

// ---------------------------------------------------------------------------
extern "C" void kernel_launch(void* const* d_in, const int* in_sizes, int n_in,
                              void* d_out, int out_size) {
    (void)in_sizes; (void)n_in; (void)out_size;
    const float* X = (const float*)d_in[0];
    const float* E = (const float*)d_in[1];

    float* outQ    = (float*)d_out;
    float* outLoss = outQ + (size_t)NROWS * DDIM;   // 16777216
    float* outIdx  = outLoss + 1;                   // 16777217

    cudaFuncSetAttribute(vq_main_mma, cudaFuncAttributeMaxDynamicSharedMemorySize,
                         DYN_SMEM);

    vq_prep<<<KCODES / 8, 256>>>(E);
    vq_main_mma<<<NROWS / M_TILE, THREADS, DYN_SMEM>>>(X, E, outQ, outIdx);
    vq_finalize<<<1, 32>>>(outLoss);
}

// round 14
// speedup vs baseline: 7.5074x; 1.4991x over previous
#include <cuda_runtime.h>
#include <cuda_bf16.h>
#include <float.h>
#include <limits.h>
#include <stdint.h>

// VectorQuantizerEMA forward (eval mode).
//   d_in[0] = X [65536, 256] f32,  d_in[1] = E [1024, 256] f32
//   out (f32): [quantized_st 16777216 | loss 1 | indices 65536]
//
// Phase 1: SINGLE-PASS bf16 scoring GEMM on mma.sync m16n8k16 (native on
//   sm_103). ||e||^2 folded via 2 augmented K-cols. Lane-local top-6 -> 24
//   disjoint candidates/row.
//   R14: OCCUPANCY 2. R8/R12/R13 showed the GEMM section is latency-bound
//   (time invariant under 3x MMA, 2x LDSM, 4x chunk size): fill stalls with
//   a 2nd resident CTA. X staging smem is reused as E buffer B after the
//   A-fragments move to registers -> dyn smem 89600, launch_bounds(256,2).
// Phase 2: warp-per-row COALESCED fp32 rescore of 24 -> top-2; exact fp64
//   on the 2 finalists (R12-validated).
// Epilogue: identical fp32 math to the reference (bit-exact).
//
// NOTE: harness compiles at compute_103 (no 'a'): tcgen05/TMEM unavailable;
// fp16.f32 mma is ptxas-emulated ~13x slower than bf16 (measured R10/R11).

#define NROWS    65536
#define DDIM     256
#define KAUG     272               // 256 + 16 (cols 256/257: -|e|^2/2 cascade)
#define KSTEPS   (KAUG / 16)       // 17
#define KCODES   1024
#define M_TILE   128
#define THREADS  256
#define WARPS    8
#define CCHUNK   32                // codes per smem chunk
#define NCHUNKS  (KCODES / CCHUNK) // 32
#define ESTRIDE  560               // bytes/row: 280 bf16 (272 used + pad)
#define X_BYTES  (M_TILE * ESTRIDE)       // 71680
#define ECH      (CCHUNK * ESTRIDE)       // 17920 per chunk
// E buffers alternate: bufA at X_BYTES (always free), bufB at 0 (X region,
// free after A-fragments are in registers). chunk c -> (c&1) ? 0 : X_BYTES.
#define DYN_SMEM (X_BYTES + ECH)          // 89600 -> occ=2

__device__ double g_loss_accum;
__device__ __align__(16) unsigned char g_Ebf[KCODES * ESTRIDE];  // 573 KB

// ---------------------------------------------------------------------------
__device__ __forceinline__ uint32_t smem_u32(const void* p) {
    uint32_t a;
    asm("{ .reg .u64 t; cvta.to.shared.u64 t, %1; cvt.u32.u64 %0, t; }"
        : "=r"(a) : "l"(p));
    return a;
}
__device__ __forceinline__ void ldmatrix_x4(uint32_t& r0, uint32_t& r1,
                                            uint32_t& r2, uint32_t& r3,
                                            uint32_t addr) {
    asm volatile("ldmatrix.sync.aligned.m8n8.x4.shared.b16 {%0,%1,%2,%3}, [%4];"
                 : "=r"(r0), "=r"(r1), "=r"(r2), "=r"(r3) : "r"(addr));
}
__device__ __forceinline__ void mma4(float c[4], const uint32_t a[4],
                                     uint32_t b0, uint32_t b1) {
    asm volatile(
        "mma.sync.aligned.m16n8k16.row.col.f32.bf16.bf16.f32 "
        "{%0,%1,%2,%3}, {%4,%5,%6,%7}, {%8,%9}, {%0,%1,%2,%3};"
        : "+f"(c[0]), "+f"(c[1]), "+f"(c[2]), "+f"(c[3])
        : "r"(a[0]), "r"(a[1]), "r"(a[2]), "r"(a[3]), "r"(b0), "r"(b1));
}
#define CP16(dst, src) \
    asm volatile("cp.async.cg.shared.global [%0], [%1], 16;" \
                 :: "r"(dst), "l"(src) : "memory")
#define CP_COMMIT() asm volatile("cp.async.commit_group;" ::: "memory")
#define CP_WAIT(n)  asm volatile("cp.async.wait_group %0;" :: "n"(n) : "memory")

// sorted top-6 by score desc (constant-index nested ifs -> predicated
// selects, register resident; NO loops/returns). Strict '>' only: in-lane
// codes ascend, so ties keep the earlier code.
__device__ __forceinline__ void ins6(float s, int c, float v[6], int ix[6]) {
    if (s > v[5]) {
        if (s > v[4]) {
            v[5] = v[4]; ix[5] = ix[4];
            if (s > v[3]) {
                v[4] = v[3]; ix[4] = ix[3];
                if (s > v[2]) {
                    v[3] = v[2]; ix[3] = ix[2];
                    if (s > v[1]) {
                        v[2] = v[1]; ix[2] = ix[1];
                        if (s > v[0]) {
                            v[1] = v[0]; ix[1] = ix[0]; v[0] = s; ix[0] = c;
                        } else { v[1] = s; ix[1] = c; }
                    } else { v[2] = s; ix[2] = c; }
                } else { v[3] = s; ix[3] = c; }
            } else { v[4] = s; ix[4] = c; }
        } else { v[5] = s; ix[5] = c; }
    }
}

// ---------------------------------------------------------------------------
// prep: E -> bf16 rows of 280 (272 used); aug cols 256/257 carry a 2-term
// bf16 cascade of -|e|^2/2. One warp per code.
// ---------------------------------------------------------------------------
__global__ void vq_prep(const float* __restrict__ E) {
    const int w = threadIdx.x >> 5, lane = threadIdx.x & 31;
    const int code = blockIdx.x * 8 + w;
    if (blockIdx.x == 0 && threadIdx.x == 0) g_loss_accum = 0.0;

    const float4* e4 = reinterpret_cast<const float4*>(E + (size_t)code * DDIM);
    float4 va = e4[lane * 2], vb = e4[lane * 2 + 1];

    __nv_bfloat162 p0 = __floats2bfloat162_rn(va.x, va.y);
    __nv_bfloat162 p1 = __floats2bfloat162_rn(va.z, va.w);
    __nv_bfloat162 p2 = __floats2bfloat162_rn(vb.x, vb.y);
    __nv_bfloat162 p3 = __floats2bfloat162_rn(vb.z, vb.w);
    uint4 out;
    out.x = *reinterpret_cast<uint32_t*>(&p0);
    out.y = *reinterpret_cast<uint32_t*>(&p1);
    out.z = *reinterpret_cast<uint32_t*>(&p2);
    out.w = *reinterpret_cast<uint32_t*>(&p3);
    *reinterpret_cast<uint4*>(g_Ebf + (size_t)code * ESTRIDE + lane * 16) = out;

    double s = 0.0;
    s += (double)va.x * va.x; s += (double)va.y * va.y;
    s += (double)va.z * va.z; s += (double)va.w * va.w;
    s += (double)vb.x * vb.x; s += (double)vb.y * vb.y;
    s += (double)vb.z * vb.z; s += (double)vb.w * vb.w;
#pragma unroll
    for (int o = 16; o >= 1; o >>= 1)
        s += __shfl_xor_sync(0xffffffffu, s, o);

    if (lane == 0) {
        double d = -0.5 * s;
        __nv_bfloat16 h1 = __float2bfloat16_rn((float)d);
        d -= (double)__bfloat162float(h1);
        __nv_bfloat16 h2 = __float2bfloat16_rn((float)d);
        uint32_t w0 = (uint32_t)*reinterpret_cast<unsigned short*>(&h1) |
                      ((uint32_t)*reinterpret_cast<unsigned short*>(&h2) << 16);
        unsigned char* b = g_Ebf + (size_t)code * ESTRIDE + 512;
        *reinterpret_cast<uint4*>(b +  0) = make_uint4(w0, 0u, 0u, 0u);
        *reinterpret_cast<uint4*>(b + 16) = make_uint4(0u, 0u, 0u, 0u);
        *reinterpret_cast<uint4*>(b + 32) = make_uint4(0u, 0u, 0u, 0u);
    }
}

// ---------------------------------------------------------------------------
__device__ __forceinline__ void prefetch_chunk(uint32_t dst, int chunk, int tid) {
    const unsigned char* src = g_Ebf + (size_t)chunk * ECH;
#pragma unroll 1
    for (int i = tid; i < ECH / 16; i += THREADS)
        CP16(dst + (uint32_t)i * 16u, src + (size_t)i * 16);
    CP_COMMIT();
}

// ---------------------------------------------------------------------------
// main: 512 CTAs x 256 threads (8 warps), occ=2; warp w owns rows w*16..+15.
// ---------------------------------------------------------------------------
__global__ __launch_bounds__(THREADS, 2)
void vq_main_mma(const float* __restrict__ X, const float* __restrict__ E,
                 float* __restrict__ outQ, float* __restrict__ outIdx) {
    extern __shared__ __align__(16) unsigned char sm[];
    __shared__ int   sCand[M_TILE][24];
    __shared__ int   sWin[M_TILE];
    __shared__ float sRed[WARPS];

    const int tid  = threadIdx.x;
    const int w    = tid >> 5;
    const int lane = tid & 31;
    const int rowbase = blockIdx.x * M_TILE;

    const uint32_t sm_u = smem_u32(sm);

    // chunk 0 -> bufA (beyond the X region; disjoint from X staging)
    prefetch_chunk(sm_u + X_BYTES, 0, tid);

    // ---- stage X tile: f32 -> bf16 rows of 280 + aug cols (1.0, 1.0) ------
    for (int i = tid; i < M_TILE * 3; i += THREADS) {
        int r = i / 3, part = i % 3;
        uint4 val = (part == 0) ? make_uint4(0x3F803F80u, 0u, 0u, 0u)
                                : make_uint4(0u, 0u, 0u, 0u);
        *reinterpret_cast<uint4*>(sm + r * ESTRIDE + 512 + part * 16) = val;
    }
    {
        const float4* xg = reinterpret_cast<const float4*>(X + (size_t)rowbase * DDIM);
        for (int i = tid; i < M_TILE * (DDIM / 4); i += THREADS) {
            int r = i >> 6, c4 = i & 63;
            float4 v = xg[i];
            __nv_bfloat162 q0 = __floats2bfloat162_rn(v.x, v.y);
            __nv_bfloat162 q1 = __floats2bfloat162_rn(v.z, v.w);
            uint2 o;
            o.x = *reinterpret_cast<uint32_t*>(&q0);
            o.y = *reinterpret_cast<uint32_t*>(&q1);
            *reinterpret_cast<uint2*>(sm + r * ESTRIDE + c4 * 8) = o;
        }
    }
    __syncthreads();

    // ---- register-resident A fragments (17 ksteps x 4 regs) ---------------
    uint32_t ah[KSTEPS][4];
    {
        uint32_t off = (uint32_t)(w * 16 + (lane & 15)) * ESTRIDE +
                       (uint32_t)((lane >> 4) * 16);
#pragma unroll
        for (int s = 0; s < KSTEPS; ++s)
            ldmatrix_x4(ah[s][0], ah[s][1], ah[s][2], ah[s][3],
                        sm_u + off + s * 32);
    }
    __syncthreads();   // ALL warps done reading X -> region 0 becomes bufB

    // chunk 1 -> bufB (the freed X region)
    prefetch_chunk(sm_u, 1, tid);

    // ---- score all codes; lane-local top-6 for rows (A, A+8) --------------
    float vA[6] = {-FLT_MAX, -FLT_MAX, -FLT_MAX, -FLT_MAX, -FLT_MAX, -FLT_MAX};
    float vB[6] = {-FLT_MAX, -FLT_MAX, -FLT_MAX, -FLT_MAX, -FLT_MAX, -FLT_MAX};
    int ixA[6] = {INT_MAX, INT_MAX, INT_MAX, INT_MAX, INT_MAX, INT_MAX};
    int ixB[6] = {INT_MAX, INT_MAX, INT_MAX, INT_MAX, INT_MAX, INT_MAX};

    // ldmatrix.x4 B address (validated R10-R13): matrices {tile k0-7,
    // tile k8-15, tile+1 k0-7, tile+1 k8-15}.
    const uint32_t brow4 = (uint32_t)(lane & 7) * ESTRIDE +
                           (uint32_t)(((lane >> 3) & 1) * 16) +
                           (uint32_t)((lane >> 4) * 8) * ESTRIDE;

    for (int chunk = 0; chunk < NCHUNKS; ++chunk) {
        const uint32_t buf = sm_u + ((chunk & 1) ? 0u : (uint32_t)X_BYTES);
        if (chunk == NCHUNKS - 1) { CP_WAIT(0); } else { CP_WAIT(1); }
        __syncthreads();

        // 4 n-tiles of 8 codes, 4 independent accumulator chains
        float ac0[4] = {0.f, 0.f, 0.f, 0.f}, ac1[4] = {0.f, 0.f, 0.f, 0.f};
        float ac2[4] = {0.f, 0.f, 0.f, 0.f}, ac3[4] = {0.f, 0.f, 0.f, 0.f};
        const uint32_t b01 = buf + brow4;              // tiles 0,1
        const uint32_t b23 = b01 + 16u * ESTRIDE;      // tiles 2,3
#pragma unroll
        for (int s = 0; s < KSTEPS; ++s) {
            uint32_t b00, b01r, b10, b11, b20, b21, b30, b31;
            ldmatrix_x4(b00, b01r, b10, b11, b01 + s * 32);
            ldmatrix_x4(b20, b21,  b30, b31, b23 + s * 32);
            mma4(ac0, ah[s], b00, b01r);
            mma4(ac1, ah[s], b10, b11);
            mma4(ac2, ah[s], b20, b21);
            mma4(ac3, ah[s], b30, b31);
        }
        const int cb = chunk * CCHUNK + (lane & 3) * 2;
        ins6(ac0[0], cb +  0, vA, ixA); ins6(ac0[1], cb +  1, vA, ixA);
        ins6(ac0[2], cb +  0, vB, ixB); ins6(ac0[3], cb +  1, vB, ixB);
        ins6(ac1[0], cb +  8, vA, ixA); ins6(ac1[1], cb +  9, vA, ixA);
        ins6(ac1[2], cb +  8, vB, ixB); ins6(ac1[3], cb +  9, vB, ixB);
        ins6(ac2[0], cb + 16, vA, ixA); ins6(ac2[1], cb + 17, vA, ixA);
        ins6(ac2[2], cb + 16, vB, ixB); ins6(ac2[3], cb + 17, vB, ixB);
        ins6(ac3[0], cb + 24, vA, ixA); ins6(ac3[1], cb + 25, vA, ixA);
        ins6(ac3[2], cb + 24, vB, ixB); ins6(ac3[3], cb + 25, vB, ixB);
        __syncthreads();              // done reading buf before refill

        if (chunk + 2 < NCHUNKS)
            prefetch_chunk(buf, chunk + 2, tid);   // refill the buffer just freed
    }

    // ---- no cross-lane merge: each lane stores its top-6 (24/row) ---------
    {
        int rA = w * 16 + (lane >> 2);
        int sl = (lane & 3) * 6;
#pragma unroll
        for (int j = 0; j < 6; ++j) {
            sCand[rA][sl + j]     = ixA[j];
            sCand[rA + 8][sl + j] = ixB[j];
        }
    }
    __syncthreads();

    // ---- Phase 2: warp-per-row COALESCED rescore (R12-validated) ----------
    for (int rr = 0; rr < M_TILE / WARPS; ++rr) {
        const int r = w * (M_TILE / WARPS) + rr;
        const float4* x4 = reinterpret_cast<const float4*>(
            X + (size_t)(rowbase + r) * DDIM);
        const float4 xa = x4[lane * 2], xb = x4[lane * 2 + 1];

        float v1 = FLT_MAX, v2 = FLT_MAX;
        int   i1 = INT_MAX, i2 = INT_MAX;
#pragma unroll 2
        for (int c = 0; c < 24; ++c) {
            const int cand = sCand[r][c];           // smem broadcast
            const float4* e4 = reinterpret_cast<const float4*>(
                E + (size_t)cand * DDIM);
            const float4 ea = e4[lane * 2], eb = e4[lane * 2 + 1];
            float d, dd = 0.0f;
            d = xa.x - ea.x; dd += d * d;  d = xa.y - ea.y; dd += d * d;
            d = xa.z - ea.z; dd += d * d;  d = xa.w - ea.w; dd += d * d;
            d = xb.x - eb.x; dd += d * d;  d = xb.y - eb.y; dd += d * d;
            d = xb.z - eb.z; dd += d * d;  d = xb.w - eb.w; dd += d * d;
#pragma unroll
            for (int o = 16; o >= 1; o >>= 1)
                dd += __shfl_xor_sync(0xffffffffu, dd, o);
            if (dd < v1 || (dd == v1 && cand < i1)) {
                v2 = v1; i2 = i1; v1 = dd; i1 = cand;
            } else if (dd < v2 || (dd == v2 && cand < i2)) {
                v2 = dd; i2 = cand;
            }
        }

        // exact fp64 on the two finalists (coalesced, warp-reduced)
        const float4* ea4 = reinterpret_cast<const float4*>(E + (size_t)i1 * DDIM);
        const float4* eb4 = reinterpret_cast<const float4*>(E + (size_t)i2 * DDIM);
        const float4 a0 = ea4[lane * 2], a1 = ea4[lane * 2 + 1];
        const float4 b0 = eb4[lane * 2], b1 = eb4[lane * 2 + 1];
        double d, dA = 0.0, dB = 0.0;
        d = (double)xa.x - (double)a0.x; dA += d * d;
        d = (double)xa.y - (double)a0.y; dA += d * d;
        d = (double)xa.z - (double)a0.z; dA += d * d;
        d = (double)xa.w - (double)a0.w; dA += d * d;
        d = (double)xb.x - (double)a1.x; dA += d * d;
        d = (double)xb.y - (double)a1.y; dA += d * d;
        d = (double)xb.z - (double)a1.z; dA += d * d;
        d = (double)xb.w - (double)a1.w; dA += d * d;
        d = (double)xa.x - (double)b0.x; dB += d * d;
        d = (double)xa.y - (double)b0.y; dB += d * d;
        d = (double)xa.z - (double)b0.z; dB += d * d;
        d = (double)xa.w - (double)b0.w; dB += d * d;
        d = (double)xb.x - (double)b1.x; dB += d * d;
        d = (double)xb.y - (double)b1.y; dB += d * d;
        d = (double)xb.z - (double)b1.z; dB += d * d;
        d = (double)xb.w - (double)b1.w; dB += d * d;
#pragma unroll
        for (int o = 16; o >= 1; o >>= 1) {
            dA += __shfl_xor_sync(0xffffffffu, dA, o);
            dB += __shfl_xor_sync(0xffffffffu, dB, o);
        }
        int win = (dA < dB || (dA == dB && i1 < i2)) ? i1 : i2;
        if (lane == 0) sWin[r] = win;
    }
    __syncthreads();

    // ---- epilogue: gather + straight-through + loss (bit-exact to R2) -----
    float lsum = 0.0f;
    {
        const float4* xg = reinterpret_cast<const float4*>(X + (size_t)rowbase * DDIM);
        for (int i = tid; i < M_TILE * (DDIM / 4); i += THREADS) {
            int r = i >> 6, c4 = i & 63;
            int idx = sWin[r];
            float4 e = *reinterpret_cast<const float4*>(E + (size_t)idx * DDIM + c4 * 4);
            float4 x = xg[i];
            float4 d, q;
            d.x = e.x - x.x; d.y = e.y - x.y; d.z = e.z - x.z; d.w = e.w - x.w;
            q.x = x.x + d.x; q.y = x.y + d.y; q.z = x.z + d.z; q.w = x.w + d.w;
            lsum += d.x * d.x + d.y * d.y + d.z * d.z + d.w * d.w;
            *reinterpret_cast<float4*>(outQ + (size_t)(rowbase + r) * DDIM + c4 * 4) = q;
        }
    }
    if (tid < M_TILE) outIdx[rowbase + tid] = (float)sWin[tid];

#pragma unroll
    for (int s = 16; s >= 1; s >>= 1)
        lsum += __shfl_xor_sync(0xffffffffu, lsum, s);
    if (lane == 0) sRed[w] = lsum;
    __syncthreads();
    if (tid == 0) {
        float s = 0.0f;
#pragma unroll
        for (int i = 0; i < WARPS; ++i) s += sRed[i];
        atomicAdd(&g_loss_accum, (double)s);
    }
}

// ---------------------------------------------------------------------------
__global__ void vq_finalize(float* __restrict__ outLoss) {
    if (threadIdx.x == 0)
        *outLoss = (float)(g_loss_accum * (1.0 / (double)((size_t)NROWS * DDIM)));
}

// ---------------------------------------------------------------------------
extern "C" void kernel_launch(void* const* d_in, const int* in_sizes, int n_in,
                              void* d_out, int out_size) {
    (void)in_sizes; (void)n_in; (void)out_size;
    const float* X = (const float*)d_in[0];
    const float* E = (const float*)d_in[1];

    float* outQ    = (float*)d_out;
    float* outLoss = outQ + (size_t)NROWS * DDIM;   // 16777216
    float* outIdx  = outLoss + 1;                   // 16777217

    cudaFuncSetAttribute(vq_main_mma, cudaFuncAttributeMaxDynamicSharedMemorySize,
                         DYN_SMEM);

    vq_prep<<<KCODES / 8, 256>>>(E);
    vq_main_mma<<<NROWS / M_TILE, THREADS, DYN_SMEM>>>(X, E, outQ, outIdx);
    vq_finalize<<<1, 32>>>(outLoss);
}

// round 15
// speedup vs baseline: 7.9623x; 1.0606x over previous
#include <cuda_runtime.h>
#include <cuda_bf16.h>
#include <float.h>
#include <limits.h>
#include <stdint.h>

// VectorQuantizerEMA forward (eval mode).
//   d_in[0] = X [65536, 256] f32,  d_in[1] = E [1024, 256] f32
//   out (f32): [quantized_st 16777216 | loss 1 | indices 65536]
//
// Phase 1: SINGLE-PASS bf16 scoring GEMM on mma.sync m16n8k16 (native on
//   sm_103). ||e||^2 folded via 2 augmented K-cols. Lane-local top-6 -> 24
//   disjoint candidates/row. Occupancy 2 (R14: -33%, latency-bound model
//   confirmed); X staging smem reused as E buffer B.
// Phase 2 (R15): warp-per-row COALESCED rescore with 4-WAY CANDIDATE ILP --
//   the 5-shfl butterfly per candidate is ~130 cyc of serial latency; four
//   interleaved chains cut the rescore critical path ~3.5x. Top-2 updates
//   applied in ascending candidate order (bit-identical to R12-R14).
//   Exact fp64 on the 2 finalists.
// Epilogue: identical fp32 math to the reference (bit-exact).
//
// NOTE: harness compiles at compute_103 (no 'a'): tcgen05/TMEM unavailable;
// fp16.f32 mma is ptxas-emulated ~13x slower than bf16 (measured R10/R11).

#define NROWS    65536
#define DDIM     256
#define KAUG     272               // 256 + 16 (cols 256/257: -|e|^2/2 cascade)
#define KSTEPS   (KAUG / 16)       // 17
#define KCODES   1024
#define M_TILE   128
#define THREADS  256
#define WARPS    8
#define CCHUNK   32                // codes per smem chunk
#define NCHUNKS  (KCODES / CCHUNK) // 32
#define ESTRIDE  560               // bytes/row: 280 bf16 (272 used + pad)
#define X_BYTES  (M_TILE * ESTRIDE)       // 71680
#define ECH      (CCHUNK * ESTRIDE)       // 17920 per chunk
// E buffers alternate: bufA at X_BYTES (always free), bufB at 0 (X region,
// free after A-fragments are in registers). chunk c -> (c&1) ? 0 : X_BYTES.
#define DYN_SMEM (X_BYTES + ECH)          // 89600 -> occ=2

__device__ double g_loss_accum;
__device__ __align__(16) unsigned char g_Ebf[KCODES * ESTRIDE];  // 573 KB

// ---------------------------------------------------------------------------
__device__ __forceinline__ uint32_t smem_u32(const void* p) {
    uint32_t a;
    asm("{ .reg .u64 t; cvta.to.shared.u64 t, %1; cvt.u32.u64 %0, t; }"
        : "=r"(a) : "l"(p));
    return a;
}
__device__ __forceinline__ void ldmatrix_x4(uint32_t& r0, uint32_t& r1,
                                            uint32_t& r2, uint32_t& r3,
                                            uint32_t addr) {
    asm volatile("ldmatrix.sync.aligned.m8n8.x4.shared.b16 {%0,%1,%2,%3}, [%4];"
                 : "=r"(r0), "=r"(r1), "=r"(r2), "=r"(r3) : "r"(addr));
}
__device__ __forceinline__ void mma4(float c[4], const uint32_t a[4],
                                     uint32_t b0, uint32_t b1) {
    asm volatile(
        "mma.sync.aligned.m16n8k16.row.col.f32.bf16.bf16.f32 "
        "{%0,%1,%2,%3}, {%4,%5,%6,%7}, {%8,%9}, {%0,%1,%2,%3};"
        : "+f"(c[0]), "+f"(c[1]), "+f"(c[2]), "+f"(c[3])
        : "r"(a[0]), "r"(a[1]), "r"(a[2]), "r"(a[3]), "r"(b0), "r"(b1));
}
#define CP16(dst, src) \
    asm volatile("cp.async.cg.shared.global [%0], [%1], 16;" \
                 :: "r"(dst), "l"(src) : "memory")
#define CP_COMMIT() asm volatile("cp.async.commit_group;" ::: "memory")
#define CP_WAIT(n)  asm volatile("cp.async.wait_group %0;" :: "n"(n) : "memory")

// sorted top-6 by score desc (constant-index nested ifs -> predicated
// selects, register resident; NO loops/returns). Strict '>' only: in-lane
// codes ascend, so ties keep the earlier code.
__device__ __forceinline__ void ins6(float s, int c, float v[6], int ix[6]) {
    if (s > v[5]) {
        if (s > v[4]) {
            v[5] = v[4]; ix[5] = ix[4];
            if (s > v[3]) {
                v[4] = v[3]; ix[4] = ix[3];
                if (s > v[2]) {
                    v[3] = v[2]; ix[3] = ix[2];
                    if (s > v[1]) {
                        v[2] = v[1]; ix[2] = ix[1];
                        if (s > v[0]) {
                            v[1] = v[0]; ix[1] = ix[0]; v[0] = s; ix[0] = c;
                        } else { v[1] = s; ix[1] = c; }
                    } else { v[2] = s; ix[2] = c; }
                } else { v[3] = s; ix[3] = c; }
            } else { v[4] = s; ix[4] = c; }
        } else { v[5] = s; ix[5] = c; }
    }
}

// top-2 (min) update; ties -> lower code index
__device__ __forceinline__ void top2min(float dd, int cand,
                                        float& v1, int& i1,
                                        float& v2, int& i2) {
    if (dd < v1 || (dd == v1 && cand < i1)) {
        v2 = v1; i2 = i1; v1 = dd; i1 = cand;
    } else if (dd < v2 || (dd == v2 && cand < i2)) {
        v2 = dd; i2 = cand;
    }
}

// ---------------------------------------------------------------------------
// prep: E -> bf16 rows of 280 (272 used); aug cols 256/257 carry a 2-term
// bf16 cascade of -|e|^2/2. One warp per code.
// ---------------------------------------------------------------------------
__global__ void vq_prep(const float* __restrict__ E) {
    const int w = threadIdx.x >> 5, lane = threadIdx.x & 31;
    const int code = blockIdx.x * 8 + w;
    if (blockIdx.x == 0 && threadIdx.x == 0) g_loss_accum = 0.0;

    const float4* e4 = reinterpret_cast<const float4*>(E + (size_t)code * DDIM);
    float4 va = e4[lane * 2], vb = e4[lane * 2 + 1];

    __nv_bfloat162 p0 = __floats2bfloat162_rn(va.x, va.y);
    __nv_bfloat162 p1 = __floats2bfloat162_rn(va.z, va.w);
    __nv_bfloat162 p2 = __floats2bfloat162_rn(vb.x, vb.y);
    __nv_bfloat162 p3 = __floats2bfloat162_rn(vb.z, vb.w);
    uint4 out;
    out.x = *reinterpret_cast<uint32_t*>(&p0);
    out.y = *reinterpret_cast<uint32_t*>(&p1);
    out.z = *reinterpret_cast<uint32_t*>(&p2);
    out.w = *reinterpret_cast<uint32_t*>(&p3);
    *reinterpret_cast<uint4*>(g_Ebf + (size_t)code * ESTRIDE + lane * 16) = out;

    double s = 0.0;
    s += (double)va.x * va.x; s += (double)va.y * va.y;
    s += (double)va.z * va.z; s += (double)va.w * va.w;
    s += (double)vb.x * vb.x; s += (double)vb.y * vb.y;
    s += (double)vb.z * vb.z; s += (double)vb.w * vb.w;
#pragma unroll
    for (int o = 16; o >= 1; o >>= 1)
        s += __shfl_xor_sync(0xffffffffu, s, o);

    if (lane == 0) {
        double d = -0.5 * s;
        __nv_bfloat16 h1 = __float2bfloat16_rn((float)d);
        d -= (double)__bfloat162float(h1);
        __nv_bfloat16 h2 = __float2bfloat16_rn((float)d);
        uint32_t w0 = (uint32_t)*reinterpret_cast<unsigned short*>(&h1) |
                      ((uint32_t)*reinterpret_cast<unsigned short*>(&h2) << 16);
        unsigned char* b = g_Ebf + (size_t)code * ESTRIDE + 512;
        *reinterpret_cast<uint4*>(b +  0) = make_uint4(w0, 0u, 0u, 0u);
        *reinterpret_cast<uint4*>(b + 16) = make_uint4(0u, 0u, 0u, 0u);
        *reinterpret_cast<uint4*>(b + 32) = make_uint4(0u, 0u, 0u, 0u);
    }
}

// ---------------------------------------------------------------------------
__device__ __forceinline__ void prefetch_chunk(uint32_t dst, int chunk, int tid) {
    const unsigned char* src = g_Ebf + (size_t)chunk * ECH;
#pragma unroll 1
    for (int i = tid; i < ECH / 16; i += THREADS)
        CP16(dst + (uint32_t)i * 16u, src + (size_t)i * 16);
    CP_COMMIT();
}

// ---------------------------------------------------------------------------
// main: 512 CTAs x 256 threads (8 warps), occ=2; warp w owns rows w*16..+15.
// ---------------------------------------------------------------------------
__global__ __launch_bounds__(THREADS, 2)
void vq_main_mma(const float* __restrict__ X, const float* __restrict__ E,
                 float* __restrict__ outQ, float* __restrict__ outIdx) {
    extern __shared__ __align__(16) unsigned char sm[];
    __shared__ int   sCand[M_TILE][24];
    __shared__ int   sWin[M_TILE];
    __shared__ float sRed[WARPS];

    const int tid  = threadIdx.x;
    const int w    = tid >> 5;
    const int lane = tid & 31;
    const int rowbase = blockIdx.x * M_TILE;

    const uint32_t sm_u = smem_u32(sm);

    // chunk 0 -> bufA (beyond the X region; disjoint from X staging)
    prefetch_chunk(sm_u + X_BYTES, 0, tid);

    // ---- stage X tile: f32 -> bf16 rows of 280 + aug cols (1.0, 1.0) ------
    for (int i = tid; i < M_TILE * 3; i += THREADS) {
        int r = i / 3, part = i % 3;
        uint4 val = (part == 0) ? make_uint4(0x3F803F80u, 0u, 0u, 0u)
                                : make_uint4(0u, 0u, 0u, 0u);
        *reinterpret_cast<uint4*>(sm + r * ESTRIDE + 512 + part * 16) = val;
    }
    {
        const float4* xg = reinterpret_cast<const float4*>(X + (size_t)rowbase * DDIM);
        for (int i = tid; i < M_TILE * (DDIM / 4); i += THREADS) {
            int r = i >> 6, c4 = i & 63;
            float4 v = xg[i];
            __nv_bfloat162 q0 = __floats2bfloat162_rn(v.x, v.y);
            __nv_bfloat162 q1 = __floats2bfloat162_rn(v.z, v.w);
            uint2 o;
            o.x = *reinterpret_cast<uint32_t*>(&q0);
            o.y = *reinterpret_cast<uint32_t*>(&q1);
            *reinterpret_cast<uint2*>(sm + r * ESTRIDE + c4 * 8) = o;
        }
    }
    __syncthreads();

    // ---- register-resident A fragments (17 ksteps x 4 regs) ---------------
    uint32_t ah[KSTEPS][4];
    {
        uint32_t off = (uint32_t)(w * 16 + (lane & 15)) * ESTRIDE +
                       (uint32_t)((lane >> 4) * 16);
#pragma unroll
        for (int s = 0; s < KSTEPS; ++s)
            ldmatrix_x4(ah[s][0], ah[s][1], ah[s][2], ah[s][3],
                        sm_u + off + s * 32);
    }
    __syncthreads();   // ALL warps done reading X -> region 0 becomes bufB

    // chunk 1 -> bufB (the freed X region)
    prefetch_chunk(sm_u, 1, tid);

    // ---- score all codes; lane-local top-6 for rows (A, A+8) --------------
    float vA[6] = {-FLT_MAX, -FLT_MAX, -FLT_MAX, -FLT_MAX, -FLT_MAX, -FLT_MAX};
    float vB[6] = {-FLT_MAX, -FLT_MAX, -FLT_MAX, -FLT_MAX, -FLT_MAX, -FLT_MAX};
    int ixA[6] = {INT_MAX, INT_MAX, INT_MAX, INT_MAX, INT_MAX, INT_MAX};
    int ixB[6] = {INT_MAX, INT_MAX, INT_MAX, INT_MAX, INT_MAX, INT_MAX};

    // ldmatrix.x4 B address (validated R10-R14): matrices {tile k0-7,
    // tile k8-15, tile+1 k0-7, tile+1 k8-15}.
    const uint32_t brow4 = (uint32_t)(lane & 7) * ESTRIDE +
                           (uint32_t)(((lane >> 3) & 1) * 16) +
                           (uint32_t)((lane >> 4) * 8) * ESTRIDE;

    for (int chunk = 0; chunk < NCHUNKS; ++chunk) {
        const uint32_t buf = sm_u + ((chunk & 1) ? 0u : (uint32_t)X_BYTES);
        if (chunk == NCHUNKS - 1) { CP_WAIT(0); } else { CP_WAIT(1); }
        __syncthreads();

        // 4 n-tiles of 8 codes, 4 independent accumulator chains
        float ac0[4] = {0.f, 0.f, 0.f, 0.f}, ac1[4] = {0.f, 0.f, 0.f, 0.f};
        float ac2[4] = {0.f, 0.f, 0.f, 0.f}, ac3[4] = {0.f, 0.f, 0.f, 0.f};
        const uint32_t b01 = buf + brow4;              // tiles 0,1
        const uint32_t b23 = b01 + 16u * ESTRIDE;      // tiles 2,3
#pragma unroll
        for (int s = 0; s < KSTEPS; ++s) {
            uint32_t b00, b01r, b10, b11, b20, b21, b30, b31;
            ldmatrix_x4(b00, b01r, b10, b11, b01 + s * 32);
            ldmatrix_x4(b20, b21,  b30, b31, b23 + s * 32);
            mma4(ac0, ah[s], b00, b01r);
            mma4(ac1, ah[s], b10, b11);
            mma4(ac2, ah[s], b20, b21);
            mma4(ac3, ah[s], b30, b31);
        }
        const int cb = chunk * CCHUNK + (lane & 3) * 2;
        ins6(ac0[0], cb +  0, vA, ixA); ins6(ac0[1], cb +  1, vA, ixA);
        ins6(ac0[2], cb +  0, vB, ixB); ins6(ac0[3], cb +  1, vB, ixB);
        ins6(ac1[0], cb +  8, vA, ixA); ins6(ac1[1], cb +  9, vA, ixA);
        ins6(ac1[2], cb +  8, vB, ixB); ins6(ac1[3], cb +  9, vB, ixB);
        ins6(ac2[0], cb + 16, vA, ixA); ins6(ac2[1], cb + 17, vA, ixA);
        ins6(ac2[2], cb + 16, vB, ixB); ins6(ac2[3], cb + 17, vB, ixB);
        ins6(ac3[0], cb + 24, vA, ixA); ins6(ac3[1], cb + 25, vA, ixA);
        ins6(ac3[2], cb + 24, vB, ixB); ins6(ac3[3], cb + 25, vB, ixB);
        __syncthreads();              // done reading buf before refill

        if (chunk + 2 < NCHUNKS)
            prefetch_chunk(buf, chunk + 2, tid);   // refill the buffer just freed
    }

    // ---- no cross-lane merge: each lane stores its top-6 (24/row) ---------
    {
        int rA = w * 16 + (lane >> 2);
        int sl = (lane & 3) * 6;
#pragma unroll
        for (int j = 0; j < 6; ++j) {
            sCand[rA][sl + j]     = ixA[j];
            sCand[rA + 8][sl + j] = ixB[j];
        }
    }
    __syncthreads();

    // ---- Phase 2: warp-per-row coalesced rescore, 4-way candidate ILP -----
    for (int rr = 0; rr < M_TILE / WARPS; ++rr) {
        const int r = w * (M_TILE / WARPS) + rr;
        const float4* x4 = reinterpret_cast<const float4*>(
            X + (size_t)(rowbase + r) * DDIM);
        const float4 xa = x4[lane * 2], xb = x4[lane * 2 + 1];

        float v1 = FLT_MAX, v2 = FLT_MAX;
        int   i1 = INT_MAX, i2 = INT_MAX;
#pragma unroll 1
        for (int c = 0; c < 24; c += 4) {
            const int c0 = sCand[r][c],     c1 = sCand[r][c + 1];
            const int c2 = sCand[r][c + 2], c3 = sCand[r][c + 3];
            const float4* e0 = reinterpret_cast<const float4*>(E + (size_t)c0 * DDIM);
            const float4* e1 = reinterpret_cast<const float4*>(E + (size_t)c1 * DDIM);
            const float4* e2 = reinterpret_cast<const float4*>(E + (size_t)c2 * DDIM);
            const float4* e3 = reinterpret_cast<const float4*>(E + (size_t)c3 * DDIM);
            const float4 e0a = e0[lane * 2], e0b = e0[lane * 2 + 1];
            const float4 e1a = e1[lane * 2], e1b = e1[lane * 2 + 1];
            const float4 e2a = e2[lane * 2], e2b = e2[lane * 2 + 1];
            const float4 e3a = e3[lane * 2], e3b = e3[lane * 2 + 1];
            float d, d0 = 0.f, d1 = 0.f, d2 = 0.f, d3 = 0.f;
            d = xa.x - e0a.x; d0 += d * d;  d = xa.y - e0a.y; d0 += d * d;
            d = xa.z - e0a.z; d0 += d * d;  d = xa.w - e0a.w; d0 += d * d;
            d = xb.x - e0b.x; d0 += d * d;  d = xb.y - e0b.y; d0 += d * d;
            d = xb.z - e0b.z; d0 += d * d;  d = xb.w - e0b.w; d0 += d * d;
            d = xa.x - e1a.x; d1 += d * d;  d = xa.y - e1a.y; d1 += d * d;
            d = xa.z - e1a.z; d1 += d * d;  d = xa.w - e1a.w; d1 += d * d;
            d = xb.x - e1b.x; d1 += d * d;  d = xb.y - e1b.y; d1 += d * d;
            d = xb.z - e1b.z; d1 += d * d;  d = xb.w - e1b.w; d1 += d * d;
            d = xa.x - e2a.x; d2 += d * d;  d = xa.y - e2a.y; d2 += d * d;
            d = xa.z - e2a.z; d2 += d * d;  d = xa.w - e2a.w; d2 += d * d;
            d = xb.x - e2b.x; d2 += d * d;  d = xb.y - e2b.y; d2 += d * d;
            d = xb.z - e2b.z; d2 += d * d;  d = xb.w - e2b.w; d2 += d * d;
            d = xa.x - e3a.x; d3 += d * d;  d = xa.y - e3a.y; d3 += d * d;
            d = xa.z - e3a.z; d3 += d * d;  d = xa.w - e3a.w; d3 += d * d;
            d = xb.x - e3b.x; d3 += d * d;  d = xb.y - e3b.y; d3 += d * d;
            d = xb.z - e3b.z; d3 += d * d;  d = xb.w - e3b.w; d3 += d * d;
            // 4 interleaved butterfly reductions (independent chains)
#pragma unroll
            for (int o = 16; o >= 1; o >>= 1) {
                d0 += __shfl_xor_sync(0xffffffffu, d0, o);
                d1 += __shfl_xor_sync(0xffffffffu, d1, o);
                d2 += __shfl_xor_sync(0xffffffffu, d2, o);
                d3 += __shfl_xor_sync(0xffffffffu, d3, o);
            }
            // sequential top-2 updates in ascending c order (== R14 result)
            top2min(d0, c0, v1, i1, v2, i2);
            top2min(d1, c1, v1, i1, v2, i2);
            top2min(d2, c2, v1, i1, v2, i2);
            top2min(d3, c3, v1, i1, v2, i2);
        }

        // exact fp64 on the two finalists (coalesced, warp-reduced)
        const float4* ea4 = reinterpret_cast<const float4*>(E + (size_t)i1 * DDIM);
        const float4* eb4 = reinterpret_cast<const float4*>(E + (size_t)i2 * DDIM);
        const float4 a0 = ea4[lane * 2], a1 = ea4[lane * 2 + 1];
        const float4 b0 = eb4[lane * 2], b1 = eb4[lane * 2 + 1];
        double d, dA = 0.0, dB = 0.0;
        d = (double)xa.x - (double)a0.x; dA += d * d;
        d = (double)xa.y - (double)a0.y; dA += d * d;
        d = (double)xa.z - (double)a0.z; dA += d * d;
        d = (double)xa.w - (double)a0.w; dA += d * d;
        d = (double)xb.x - (double)a1.x; dA += d * d;
        d = (double)xb.y - (double)a1.y; dA += d * d;
        d = (double)xb.z - (double)a1.z; dA += d * d;
        d = (double)xb.w - (double)a1.w; dA += d * d;
        d = (double)xa.x - (double)b0.x; dB += d * d;
        d = (double)xa.y - (double)b0.y; dB += d * d;
        d = (double)xa.z - (double)b0.z; dB += d * d;
        d = (double)xa.w - (double)b0.w; dB += d * d;
        d = (double)xb.x - (double)b1.x; dB += d * d;
        d = (double)xb.y - (double)b1.y; dB += d * d;
        d = (double)xb.z - (double)b1.z; dB += d * d;
        d = (double)xb.w - (double)b1.w; dB += d * d;
#pragma unroll
        for (int o = 16; o >= 1; o >>= 1) {
            dA += __shfl_xor_sync(0xffffffffu, dA, o);
            dB += __shfl_xor_sync(0xffffffffu, dB, o);
        }
        int win = (dA < dB || (dA == dB && i1 < i2)) ? i1 : i2;
        if (lane == 0) sWin[r] = win;
    }
    __syncthreads();

    // ---- epilogue: gather + straight-through + loss (bit-exact to R2) -----
    float lsum = 0.0f;
    {
        const float4* xg = reinterpret_cast<const float4*>(X + (size_t)rowbase * DDIM);
        for (int i = tid; i < M_TILE * (DDIM / 4); i += THREADS) {
            int r = i >> 6, c4 = i & 63;
            int idx = sWin[r];
            float4 e = *reinterpret_cast<const float4*>(E + (size_t)idx * DDIM + c4 * 4);
            float4 x = xg[i];
            float4 d, q;
            d.x = e.x - x.x; d.y = e.y - x.y; d.z = e.z - x.z; d.w = e.w - x.w;
            q.x = x.x + d.x; q.y = x.y + d.y; q.z = x.z + d.z; q.w = x.w + d.w;
            lsum += d.x * d.x + d.y * d.y + d.z * d.z + d.w * d.w;
            *reinterpret_cast<float4*>(outQ + (size_t)(rowbase + r) * DDIM + c4 * 4) = q;
        }
    }
    if (tid < M_TILE) outIdx[rowbase + tid] = (float)sWin[tid];

#pragma unroll
    for (int s = 16; s >= 1; s >>= 1)
        lsum += __shfl_xor_sync(0xffffffffu, lsum, s);
    if (lane == 0) sRed[w] = lsum;
    __syncthreads();
    if (tid == 0) {
        float s = 0.0f;
#pragma unroll
        for (int i = 0; i < WARPS; ++i) s += sRed[i];
        atomicAdd(&g_loss_accum, (double)s);
    }
}

// ---------------------------------------------------------------------------
__global__ void vq_finalize(float* __restrict__ outLoss) {
    if (threadIdx.x == 0)
        *outLoss = (float)(g_loss_accum * (1.0 / (double)((size_t)NROWS * DDIM)));
}

// ---------------------------------------------------------------------------
extern "C" void kernel_launch(void* const* d_in, const int* in_sizes, int n_in,
                              void* d_out, int out_size) {
    (void)in_sizes; (void)n_in; (void)out_size;
    const float* X = (const float*)d_in[0];
    const float* E = (const float*)d_in[1];

    float* outQ    = (float*)d_out;
    float* outLoss = outQ + (size_t)NROWS * DDIM;   // 16777216
    float* outIdx  = outLoss + 1;                   // 16777217

    cudaFuncSetAttribute(vq_main_mma, cudaFuncAttributeMaxDynamicSharedMemorySize,
                         DYN_SMEM);

    vq_prep<<<KCODES / 8, 256>>>(E);
    vq_main_mma<<<NROWS / M_TILE, THREADS, DYN_SMEM>>>(X, E, outQ, outIdx);
    vq_finalize<<<1, 32>>>(outLoss);
}